// round 7
// baseline (speedup 1.0000x reference)
#include <cuda_runtime.h>
#include <cuda_bf16.h>
#include <math.h>
#include <stdint.h>

// Problem constants
#define T_STEPS 64
#define BATCH   32
#define HSZ     512
#define VSZ     32000
#define GSZ     2048            // 4*HSZ
#define MROWS   2048            // T*B

// ---------------- scratch (device globals; no allocations allowed) ----------
__device__ float          g_X[MROWS * GSZ];          // 16 MB: x-part of gates
__device__ float          g_h[2][BATCH * HSZ];       // double-buffered hidden
__device__ float          g_c[BATCH * HSZ];          // cell state
__device__ __nv_bfloat16  g_hout[MROWS * HSZ];       // all h_t in bf16 (GEMM2 A)
__device__ __nv_bfloat16  g_woutb[VSZ * HSZ];        // W_out in bf16 (GEMM2 B)
__device__ int            g_is64;                    // dst dtype flag

// ---------------- dtype detect for dst (int64 vs int32) ---------------------
// int64 little-endian with values < 2^31 => every odd 32-bit word is 0.
// Only reads the first 2048 words (safe for both dtypes).
__global__ void detect_kernel(const int* __restrict__ dstw) {
    __shared__ int ok;
    if (threadIdx.x == 0) ok = 1;
    __syncthreads();
    for (int i = threadIdx.x; i < 1024; i += blockDim.x)
        if (dstw[2 * i + 1] != 0) ok = 0;
    __syncthreads();
    if (threadIdx.x == 0) g_is64 = ok;
}

// ---------------- prep: W_out -> bf16, copy h0/c0 ---------------------------
__global__ void prep_kernel(const float* __restrict__ wout,
                            const float* __restrict__ h0,
                            const float* __restrict__ c0) {
    int i = blockIdx.x * blockDim.x + threadIdx.x;
    if (i < VSZ * HSZ) g_woutb[i] = __float2bfloat16(wout[i]);
    if (i < BATCH * HSZ) { g_h[0][i] = h0[i]; g_c[i] = c0[i]; }
}

// ---------------- GEMM1: X = emb[dst] @ W_ih^T + (b_ih + b_hh) --------------
// M=2048 (t*B+b), N=2048, K=512. fp32, 64x64 tiles, 4x4 per thread.
__global__ void __launch_bounds__(256) gemm1_kernel(
    const float* __restrict__ emb, const float* __restrict__ Wih,
    const float* __restrict__ bih, const float* __restrict__ bhh,
    const int* __restrict__ dstw) {
    __shared__ float As[64][17];
    __shared__ float Bs[64][17];
    __shared__ int   ridx[64];

    const int m0 = blockIdx.y * 64;
    const int n0 = blockIdx.x * 64;
    const int tid = threadIdx.x;

    if (tid < 64) {
        int m = m0 + tid;
        ridx[tid] = g_is64 ? dstw[2 * m] : dstw[m];
    }

    const int tx = tid & 15, ty = tid >> 4;
    const int lr = tid >> 2, kq = (tid & 3) * 4;
    float acc[4][4] = {};

    for (int kc = 0; kc < HSZ; kc += 16) {
        __syncthreads();
        {
            float4 av = *(const float4*)(emb + (size_t)ridx[lr] * HSZ + kc + kq);
            As[lr][kq + 0] = av.x; As[lr][kq + 1] = av.y;
            As[lr][kq + 2] = av.z; As[lr][kq + 3] = av.w;
            float4 bv = *(const float4*)(Wih + (size_t)(n0 + lr) * HSZ + kc + kq);
            Bs[lr][kq + 0] = bv.x; Bs[lr][kq + 1] = bv.y;
            Bs[lr][kq + 2] = bv.z; Bs[lr][kq + 3] = bv.w;
        }
        __syncthreads();
        #pragma unroll
        for (int k = 0; k < 16; k++) {
            float a[4], b[4];
            #pragma unroll
            for (int i = 0; i < 4; i++) a[i] = As[ty * 4 + i][k];
            #pragma unroll
            for (int j = 0; j < 4; j++) b[j] = Bs[tx * 4 + j][k];
            #pragma unroll
            for (int i = 0; i < 4; i++)
                #pragma unroll
                for (int j = 0; j < 4; j++)
                    acc[i][j] += a[i] * b[j];
        }
    }
    #pragma unroll
    for (int i = 0; i < 4; i++) {
        int m = m0 + ty * 4 + i;
        #pragma unroll
        for (int j = 0; j < 4; j++) {
            int n = n0 + tx * 4 + j;
            g_X[(size_t)m * GSZ + n] = acc[i][j] + bih[n] + bhh[n];
        }
    }
}

// ---------------- LSTM step (one launch per t) ------------------------------
// 128 blocks, block owns 4 j-indices (16 gate rows). Warp w computes gate
// rows lr=w and lr=w+8 for all 32 batches. Then threads 0..127 do the cell
// update for (b, j). h double-buffered across launches (cross-block race).
__global__ void __launch_bounds__(256) lstm_step_kernel(
    const float* __restrict__ Whh, int t) {
    __shared__ float Hs[BATCH][68];
    __shared__ float Ws[16][68];
    __shared__ float gsm[16][BATCH];

    const float* __restrict__ hin = g_h[t & 1];
    float* __restrict__ hnext = g_h[(t + 1) & 1];

    const int tid = threadIdx.x;
    const int w = tid >> 5, lane = tid & 31;
    const int j0 = blockIdx.x * 4;
    const int lr0 = w, lr1 = w + 8;

    const int hb = tid >> 3, hk = (tid & 7) * 8;
    const int wl = tid >> 4, wk = (tid & 15) * 4;
    const int wrow = ((wl >> 2) << 9) + j0 + (wl & 3);  // 512*(lr>>2)+j0+(lr&3)

    float acc0 = 0.f, acc1 = 0.f;

    for (int kc = 0; kc < HSZ; kc += 64) {
        __syncthreads();
        float4 v0 = *(const float4*)(hin + hb * HSZ + kc + hk);
        float4 v1 = *(const float4*)(hin + hb * HSZ + kc + hk + 4);
        *(float4*)&Hs[hb][hk] = v0;
        *(float4*)&Hs[hb][hk + 4] = v1;
        float4 wv = *(const float4*)(Whh + (size_t)wrow * HSZ + kc + wk);
        *(float4*)&Ws[wl][wk] = wv;
        __syncthreads();
        #pragma unroll
        for (int k = 0; k < 64; k += 4) {
            float4 hv = *(const float4*)&Hs[lane][k];
            float4 wa = *(const float4*)&Ws[lr0][k];
            float4 wb = *(const float4*)&Ws[lr1][k];
            acc0 += hv.x * wa.x + hv.y * wa.y + hv.z * wa.z + hv.w * wa.w;
            acc1 += hv.x * wb.x + hv.y * wb.y + hv.z * wb.z + hv.w * wb.w;
        }
    }
    gsm[lr0][lane] = acc0;
    gsm[lr1][lane] = acc1;
    __syncthreads();

    if (tid < 128) {
        int b = tid & 31, jj = tid >> 5;
        int j = j0 + jj;
        const float* Xrow = g_X + (size_t)(t * BATCH + b) * GSZ;
        float gi = Xrow[j]           + gsm[jj][b];
        float gf = Xrow[HSZ + j]     + gsm[4 + jj][b];
        float gg = Xrow[2 * HSZ + j] + gsm[8 + jj][b];
        float go = Xrow[3 * HSZ + j] + gsm[12 + jj][b];
        float si = 1.f / (1.f + expf(-gi));
        float sf = 1.f / (1.f + expf(-gf));
        float so = 1.f / (1.f + expf(-go));
        float tg = tanhf(gg);
        float cn = sf * g_c[b * HSZ + j] + si * tg;
        float hn = so * tanhf(cn);
        g_c[b * HSZ + j] = cn;
        hnext[b * HSZ + j] = hn;
        g_hout[(size_t)(t * BATCH + b) * HSZ + j] = __float2bfloat16(hn);
    }
}

// ---------------- GEMM2: logits = H_out @ W_out^T + b_out (bf16 mma) --------
__device__ __forceinline__ void mma16816(float* c, const uint32_t* a,
                                         uint32_t b0, uint32_t b1) {
    asm volatile(
        "mma.sync.aligned.m16n8k16.row.col.f32.bf16.bf16.f32 "
        "{%0,%1,%2,%3}, {%4,%5,%6,%7}, {%8,%9}, {%0,%1,%2,%3};\n"
        : "+f"(c[0]), "+f"(c[1]), "+f"(c[2]), "+f"(c[3])
        : "r"(a[0]), "r"(a[1]), "r"(a[2]), "r"(a[3]), "r"(b0), "r"(b1));
}

// Block tile 128x128, BK=16, 8 warps as 4(m) x 2(n); warp tile 32x64.
// Writes directly to d_out at the transposed (b, t) row with b_out added.
__global__ void __launch_bounds__(256) gemm2_kernel(
    const float* __restrict__ b_out, float* __restrict__ out) {
    __shared__ __nv_bfloat16 As[128][24];   // 12-word row stride: conflict-free
    __shared__ __nv_bfloat16 Bs[128][24];

    const int tid = threadIdx.x;
    const int m0 = blockIdx.y * 128;
    const int n0 = blockIdx.x * 128;
    const int warp = tid >> 5, lane = tid & 31;
    const int wm = warp & 3, wn = warp >> 2;
    const int g = lane >> 2, tg = lane & 3;
    const int lr = tid >> 1, hf = tid & 1;

    float acc[2][8][4] = {};

    for (int kc = 0; kc < HSZ; kc += 16) {
        __syncthreads();
        *(uint4*)&As[lr][hf * 8] =
            *(const uint4*)(g_hout + (size_t)(m0 + lr) * HSZ + kc + hf * 8);
        *(uint4*)&Bs[lr][hf * 8] =
            *(const uint4*)(g_woutb + (size_t)(n0 + lr) * HSZ + kc + hf * 8);
        __syncthreads();

        uint32_t a[2][4];
        #pragma unroll
        for (int mi = 0; mi < 2; mi++) {
            int rb = wm * 32 + mi * 16;
            a[mi][0] = *(const uint32_t*)&As[rb + g][2 * tg];
            a[mi][1] = *(const uint32_t*)&As[rb + g + 8][2 * tg];
            a[mi][2] = *(const uint32_t*)&As[rb + g][2 * tg + 8];
            a[mi][3] = *(const uint32_t*)&As[rb + g + 8][2 * tg + 8];
        }
        #pragma unroll
        for (int ni = 0; ni < 8; ni++) {
            uint32_t b0 = *(const uint32_t*)&Bs[wn * 64 + ni * 8 + g][2 * tg];
            uint32_t b1 = *(const uint32_t*)&Bs[wn * 64 + ni * 8 + g][2 * tg + 8];
            mma16816(acc[0][ni], a[0], b0, b1);
            mma16816(acc[1][ni], a[1], b0, b1);
        }
    }

    // Epilogue: m = t*32 + b  ->  output row = b*64 + t
    #pragma unroll
    for (int mi = 0; mi < 2; mi++) {
        int mbase = m0 + wm * 32 + mi * 16;
        #pragma unroll
        for (int ni = 0; ni < 8; ni++) {
            int n = n0 + wn * 64 + ni * 8 + 2 * tg;
            float bo0 = b_out[n], bo1 = b_out[n + 1];
            int m_a = mbase + g;
            int row_a = (m_a & 31) * T_STEPS + (m_a >> 5);
            float2 va; va.x = acc[mi][ni][0] + bo0; va.y = acc[mi][ni][1] + bo1;
            *(float2*)(out + (size_t)row_a * VSZ + n) = va;
            int m_b = mbase + g + 8;
            int row_b = (m_b & 31) * T_STEPS + (m_b >> 5);
            float2 vb; vb.x = acc[mi][ni][2] + bo0; vb.y = acc[mi][ni][3] + bo1;
            *(float2*)(out + (size_t)row_b * VSZ + n) = vb;
        }
    }
}

// ---------------- log_softmax in place over each 32000-row ------------------
__global__ void __launch_bounds__(256) logsoftmax_kernel(float* __restrict__ out) {
    __shared__ float sm[256], ss[256];
    float* row = out + (size_t)blockIdx.x * VSZ;
    const int tid = threadIdx.x;

    float m = -3.4e38f, s = 0.f;
    for (int i = tid; i < VSZ; i += 256) {
        float x = row[i];
        if (x > m) { s = s * expf(m - x) + 1.f; m = x; }
        else       { s += expf(x - m); }
    }
    sm[tid] = m; ss[tid] = s;
    __syncthreads();
    for (int off = 128; off > 0; off >>= 1) {
        if (tid < off) {
            float m2 = sm[tid + off], s2 = ss[tid + off];
            float mo = sm[tid];
            float M = fmaxf(mo, m2);
            ss[tid] = ss[tid] * expf(mo - M) + s2 * expf(m2 - M);
            sm[tid] = M;
        }
        __syncthreads();
    }
    float logZ = sm[0] + logf(ss[0]);
    for (int i = tid; i < VSZ; i += 256) row[i] = row[i] - logZ;
}

// ---------------- launch ----------------------------------------------------
extern "C" void kernel_launch(void* const* d_in, const int* in_sizes, int n_in,
                              void* d_out, int out_size) {
    // inputs: 0 context (unused), 1 h0, 2 c0, 3 emb, 4 W_ih, 5 W_hh,
    //         6 b_ih, 7 b_hh, 8 W_out, 9 b_out, 10 dst
    const float* h0   = (const float*)d_in[1];
    const float* c0   = (const float*)d_in[2];
    const float* emb  = (const float*)d_in[3];
    const float* Wih  = (const float*)d_in[4];
    const float* Whh  = (const float*)d_in[5];
    const float* bih  = (const float*)d_in[6];
    const float* bhh  = (const float*)d_in[7];
    const float* Wout = (const float*)d_in[8];
    const float* bout = (const float*)d_in[9];
    const int*   dstw = (const int*)d_in[10];
    float* out = (float*)d_out;

    detect_kernel<<<1, 256>>>(dstw);
    prep_kernel<<<(VSZ * HSZ + 255) / 256, 256>>>(Wout, h0, c0);
    gemm1_kernel<<<dim3(GSZ / 64, MROWS / 64), 256>>>(emb, Wih, bih, bhh, dstw);
    for (int t = 0; t < T_STEPS; t++)
        lstm_step_kernel<<<128, 256>>>(Whh, t);
    gemm2_kernel<<<dim3(VSZ / 128, MROWS / 128), 256>>>(bout, out);
    logsoftmax_kernel<<<MROWS, 256>>>(out);
}

// round 8
// speedup vs baseline: 1.2293x; 1.2293x over previous
#include <cuda_runtime.h>
#include <cuda_bf16.h>
#include <math.h>
#include <stdint.h>

// Problem constants
#define T_STEPS 64
#define BATCH   32
#define HSZ     512
#define VSZ     32000
#define GSZ     2048            // 4*HSZ
#define MROWS   2048            // T*B
#define NBLK    128             // persistent LSTM grid (<=148 SMs, all resident)

// ---------------- scratch (device globals; no allocations allowed) ----------
__device__ float          g_X[MROWS * GSZ];          // 16 MB: x-part of gates
__device__ float          g_h[2][BATCH * HSZ];       // double-buffered hidden
__device__ float          g_c[BATCH * HSZ];          // cell state (init only)
__device__ __nv_bfloat16  g_hout[MROWS * HSZ];       // all h_t in bf16 (GEMM2 A)
__device__ __nv_bfloat16  g_woutb[VSZ * HSZ];        // W_out in bf16 (GEMM2 B)
__device__ int            g_is64;                    // dst dtype flag
__device__ unsigned       g_bar;                     // grid barrier counter

// ---------------- dtype detect for dst (int64 vs int32) ---------------------
__global__ void detect_kernel(const int* __restrict__ dstw) {
    __shared__ int ok;
    if (threadIdx.x == 0) ok = 1;
    __syncthreads();
    for (int i = threadIdx.x; i < 1024; i += blockDim.x)
        if (dstw[2 * i + 1] != 0) ok = 0;
    __syncthreads();
    if (threadIdx.x == 0) g_is64 = ok;
}

// ---------------- prep: W_out -> bf16, copy h0/c0, reset barrier ------------
__global__ void prep_kernel(const float* __restrict__ wout,
                            const float* __restrict__ h0,
                            const float* __restrict__ c0) {
    int i = blockIdx.x * blockDim.x + threadIdx.x;
    if (i == 0) g_bar = 0u;
    if (i < VSZ * HSZ) g_woutb[i] = __float2bfloat16(wout[i]);
    if (i < BATCH * HSZ) { g_h[0][i] = h0[i]; g_c[i] = c0[i]; }
}

// ---------------- GEMM1: X = emb[dst] @ W_ih^T + (b_ih + b_hh) --------------
__global__ void __launch_bounds__(256) gemm1_kernel(
    const float* __restrict__ emb, const float* __restrict__ Wih,
    const float* __restrict__ bih, const float* __restrict__ bhh,
    const int* __restrict__ dstw) {
    __shared__ float As[64][17];
    __shared__ float Bs[64][17];
    __shared__ int   ridx[64];

    const int m0 = blockIdx.y * 64;
    const int n0 = blockIdx.x * 64;
    const int tid = threadIdx.x;

    if (tid < 64) {
        int m = m0 + tid;
        ridx[tid] = g_is64 ? dstw[2 * m] : dstw[m];
    }

    const int tx = tid & 15, ty = tid >> 4;
    const int lr = tid >> 2, kq = (tid & 3) * 4;
    float acc[4][4] = {};

    for (int kc = 0; kc < HSZ; kc += 16) {
        __syncthreads();
        {
            float4 av = *(const float4*)(emb + (size_t)ridx[lr] * HSZ + kc + kq);
            As[lr][kq + 0] = av.x; As[lr][kq + 1] = av.y;
            As[lr][kq + 2] = av.z; As[lr][kq + 3] = av.w;
            float4 bv = *(const float4*)(Wih + (size_t)(n0 + lr) * HSZ + kc + kq);
            Bs[lr][kq + 0] = bv.x; Bs[lr][kq + 1] = bv.y;
            Bs[lr][kq + 2] = bv.z; Bs[lr][kq + 3] = bv.w;
        }
        __syncthreads();
        #pragma unroll
        for (int k = 0; k < 16; k++) {
            float a[4], b[4];
            #pragma unroll
            for (int i = 0; i < 4; i++) a[i] = As[ty * 4 + i][k];
            #pragma unroll
            for (int j = 0; j < 4; j++) b[j] = Bs[tx * 4 + j][k];
            #pragma unroll
            for (int i = 0; i < 4; i++)
                #pragma unroll
                for (int j = 0; j < 4; j++)
                    acc[i][j] += a[i] * b[j];
        }
    }
    #pragma unroll
    for (int i = 0; i < 4; i++) {
        int m = m0 + ty * 4 + i;
        #pragma unroll
        for (int j = 0; j < 4; j++) {
            int n = n0 + tx * 4 + j;
            g_X[(size_t)m * GSZ + n] = acc[i][j] + bih[n] + bhh[n];
        }
    }
}

// ---------------- persistent LSTM: all 64 steps in ONE kernel ---------------
// 128 blocks x 256 threads, 1 block/SM, all co-resident.
// Block owns j0=blockIdx*4 -> 16 gate rows {g*512+j0+jj}. c lives in registers
// of threads 0..127 for the whole recurrence. Grid barrier: atomic counter.
//
// Compute: warp w: kh=w>>2 selects K-half, rg=w&3 selects 4 local rows.
// lane = batch. h tile in smem, XOR-swizzled so the 32-lane LDS.128 is
// conflict-free (4 wavefronts); W rows are all-lane broadcast LDS (1 wf).
__global__ void __launch_bounds__(256) lstm_persistent_kernel(
    const float* __restrict__ Whh) {
    extern __shared__ float sdyn[];
    float*  Ws  = sdyn;                                  // [16][516]
    float4* Hs  = (float4*)(sdyn + 16 * 516);            // [32*128] swizzled
    float*  psm = (float*)(Hs + 32 * 128);               // [2][16][33]

    const int tid = threadIdx.x;
    const int j0  = blockIdx.x * 4;
    const int w   = tid >> 5, lane = tid & 31;
    const int kh  = w >> 2, rg = w & 3;
    const int sw  = lane & 7;

    // Load this block's Whh slice into smem once (16 rows x 512).
    {
        int lr = tid >> 4;                 // 0..15
        int kq = (tid & 15) * 4;           // 0..60
        int grow = ((lr >> 2) << 9) + j0 + (lr & 3);
        #pragma unroll
        for (int kc = 0; kc < HSZ; kc += 64)
            *(float4*)&Ws[lr * 516 + kc + kq] =
                *(const float4*)(Whh + (size_t)grow * HSZ + kc + kq);
    }

    // Persistent cell state in registers (threads 0..127 own fixed (b, j)).
    const int b_my = tid & 31, jj_my = tid >> 5;
    float c_reg = 0.f;
    if (tid < 128) c_reg = g_c[b_my * HSZ + j0 + jj_my];

    for (int t = 0; t < T_STEPS; t++) {
        // Prefetch X for this step (no cross-step hazard; overlaps the spin).
        float x0 = 0.f, x1 = 0.f, x2 = 0.f, x3 = 0.f;
        if (tid < 128) {
            const float* Xr = g_X + (size_t)(t * BATCH + b_my) * GSZ + j0 + jj_my;
            x0 = Xr[0]; x1 = Xr[HSZ]; x2 = Xr[2 * HSZ]; x3 = Xr[3 * HSZ];
        }

        // Grid barrier: wait until every block finished step t-1.
        if (t > 0) {
            if (tid == 0) {
                unsigned target = (unsigned)NBLK * (unsigned)t;
                while (*(volatile unsigned*)&g_bar < target) { }
            }
            __syncthreads();
            __threadfence();
        }

        // Load h(t) -> swizzled smem (L1 bypass: written by other SMs).
        {
            const float4* hsrc = (const float4*)g_h[t & 1];
            #pragma unroll
            for (int j = 0; j < 16; j++) {
                int fidx = tid + j * 256;          // 0..4095
                int b = fidx >> 7, kk = fidx & 127;
                Hs[b * 128 + (kk ^ (b & 7))] = __ldcg(hsrc + fidx);
            }
        }
        __syncthreads();

        // Partial gates: 4 rows x 1 batch per lane over this warp's K-half.
        {
            float a0 = 0.f, a1 = 0.f, a2 = 0.f, a3 = 0.f;
            const float4* HsL = Hs + lane * 128;
            const float* W0 = Ws + (rg * 4 + 0) * 516 + kh * 256;
            const float* W1 = Ws + (rg * 4 + 1) * 516 + kh * 256;
            const float* W2 = Ws + (rg * 4 + 2) * 516 + kh * 256;
            const float* W3 = Ws + (rg * 4 + 3) * 516 + kh * 256;
            #pragma unroll 8
            for (int kk = 0; kk < 64; kk++) {
                float4 hv = HsL[(kh * 64 + kk) ^ sw];
                float4 v0 = *(const float4*)(W0 + kk * 4);
                float4 v1 = *(const float4*)(W1 + kk * 4);
                float4 v2 = *(const float4*)(W2 + kk * 4);
                float4 v3 = *(const float4*)(W3 + kk * 4);
                a0 += hv.x * v0.x + hv.y * v0.y + hv.z * v0.z + hv.w * v0.w;
                a1 += hv.x * v1.x + hv.y * v1.y + hv.z * v1.z + hv.w * v1.w;
                a2 += hv.x * v2.x + hv.y * v2.y + hv.z * v2.z + hv.w * v2.w;
                a3 += hv.x * v3.x + hv.y * v3.y + hv.z * v3.z + hv.w * v3.w;
            }
            psm[(kh * 16 + rg * 4 + 0) * 33 + lane] = a0;
            psm[(kh * 16 + rg * 4 + 1) * 33 + lane] = a1;
            psm[(kh * 16 + rg * 4 + 2) * 33 + lane] = a2;
            psm[(kh * 16 + rg * 4 + 3) * 33 + lane] = a3;
        }
        __syncthreads();

        // Cell update (threads 0..127; each owns fixed (b_my, j0+jj_my)).
        if (tid < 128) {
            float gi = x0 + psm[(0 * 4 + jj_my) * 33 + b_my]
                          + psm[(16 + 0 * 4 + jj_my) * 33 + b_my];
            float gf = x1 + psm[(1 * 4 + jj_my) * 33 + b_my]
                          + psm[(16 + 1 * 4 + jj_my) * 33 + b_my];
            float gg = x2 + psm[(2 * 4 + jj_my) * 33 + b_my]
                          + psm[(16 + 2 * 4 + jj_my) * 33 + b_my];
            float go = x3 + psm[(3 * 4 + jj_my) * 33 + b_my]
                          + psm[(16 + 3 * 4 + jj_my) * 33 + b_my];
            float si = 1.f / (1.f + expf(-gi));
            float sf = 1.f / (1.f + expf(-gf));
            float so = 1.f / (1.f + expf(-go));
            float cn = sf * c_reg + si * tanhf(gg);
            float hn = so * tanhf(cn);
            c_reg = cn;
            __stcg(&g_h[(t + 1) & 1][b_my * HSZ + j0 + jj_my], hn);
            g_hout[(size_t)(t * BATCH + b_my) * HSZ + j0 + jj_my] =
                __float2bfloat16(hn);
            __threadfence();   // release h before the barrier arrive
        }
        __syncthreads();
        if (tid == 0) atomicAdd(&g_bar, 1u);
    }
}

// ---------------- GEMM2: logits = H_out @ W_out^T + b_out (bf16 mma) --------
__device__ __forceinline__ void mma16816(float* c, const uint32_t* a,
                                         uint32_t b0, uint32_t b1) {
    asm volatile(
        "mma.sync.aligned.m16n8k16.row.col.f32.bf16.bf16.f32 "
        "{%0,%1,%2,%3}, {%4,%5,%6,%7}, {%8,%9}, {%0,%1,%2,%3};\n"
        : "+f"(c[0]), "+f"(c[1]), "+f"(c[2]), "+f"(c[3])
        : "r"(a[0]), "r"(a[1]), "r"(a[2]), "r"(a[3]), "r"(b0), "r"(b1));
}

__global__ void __launch_bounds__(256) gemm2_kernel(
    const float* __restrict__ b_out, float* __restrict__ out) {
    __shared__ __nv_bfloat16 As[128][24];
    __shared__ __nv_bfloat16 Bs[128][24];

    const int tid = threadIdx.x;
    const int m0 = blockIdx.y * 128;
    const int n0 = blockIdx.x * 128;
    const int warp = tid >> 5, lane = tid & 31;
    const int wm = warp & 3, wn = warp >> 2;
    const int g = lane >> 2, tg = lane & 3;
    const int lr = tid >> 1, hf = tid & 1;

    float acc[2][8][4] = {};

    for (int kc = 0; kc < HSZ; kc += 16) {
        __syncthreads();
        *(uint4*)&As[lr][hf * 8] =
            *(const uint4*)(g_hout + (size_t)(m0 + lr) * HSZ + kc + hf * 8);
        *(uint4*)&Bs[lr][hf * 8] =
            *(const uint4*)(g_woutb + (size_t)(n0 + lr) * HSZ + kc + hf * 8);
        __syncthreads();

        uint32_t a[2][4];
        #pragma unroll
        for (int mi = 0; mi < 2; mi++) {
            int rb = wm * 32 + mi * 16;
            a[mi][0] = *(const uint32_t*)&As[rb + g][2 * tg];
            a[mi][1] = *(const uint32_t*)&As[rb + g + 8][2 * tg];
            a[mi][2] = *(const uint32_t*)&As[rb + g][2 * tg + 8];
            a[mi][3] = *(const uint32_t*)&As[rb + g + 8][2 * tg + 8];
        }
        #pragma unroll
        for (int ni = 0; ni < 8; ni++) {
            uint32_t b0 = *(const uint32_t*)&Bs[wn * 64 + ni * 8 + g][2 * tg];
            uint32_t b1 = *(const uint32_t*)&Bs[wn * 64 + ni * 8 + g][2 * tg + 8];
            mma16816(acc[0][ni], a[0], b0, b1);
            mma16816(acc[1][ni], a[1], b0, b1);
        }
    }

    // Epilogue: m = t*32 + b  ->  output row = b*64 + t
    #pragma unroll
    for (int mi = 0; mi < 2; mi++) {
        int mbase = m0 + wm * 32 + mi * 16;
        #pragma unroll
        for (int ni = 0; ni < 8; ni++) {
            int n = n0 + wn * 64 + ni * 8 + 2 * tg;
            float bo0 = b_out[n], bo1 = b_out[n + 1];
            int m_a = mbase + g;
            int row_a = (m_a & 31) * T_STEPS + (m_a >> 5);
            float2 va; va.x = acc[mi][ni][0] + bo0; va.y = acc[mi][ni][1] + bo1;
            *(float2*)(out + (size_t)row_a * VSZ + n) = va;
            int m_b = mbase + g + 8;
            int row_b = (m_b & 31) * T_STEPS + (m_b >> 5);
            float2 vb; vb.x = acc[mi][ni][2] + bo0; vb.y = acc[mi][ni][3] + bo1;
            *(float2*)(out + (size_t)row_b * VSZ + n) = vb;
        }
    }
}

// ---------------- log_softmax in place over each 32000-row ------------------
__global__ void __launch_bounds__(256) logsoftmax_kernel(float* __restrict__ out) {
    __shared__ float sm[256], ss[256];
    float* row = out + (size_t)blockIdx.x * VSZ;
    const int tid = threadIdx.x;

    float m = -3.4e38f, s = 0.f;
    for (int i = tid; i < VSZ; i += 256) {
        float x = row[i];
        if (x > m) { s = s * expf(m - x) + 1.f; m = x; }
        else       { s += expf(x - m); }
    }
    sm[tid] = m; ss[tid] = s;
    __syncthreads();
    for (int off = 128; off > 0; off >>= 1) {
        if (tid < off) {
            float m2 = sm[tid + off], s2 = ss[tid + off];
            float mo = sm[tid];
            float M = fmaxf(mo, m2);
            ss[tid] = ss[tid] * expf(mo - M) + s2 * expf(m2 - M);
            sm[tid] = M;
        }
        __syncthreads();
    }
    float logZ = sm[0] + logf(ss[0]);
    for (int i = tid; i < VSZ; i += 256) row[i] = row[i] - logZ;
}

// ---------------- launch ----------------------------------------------------
extern "C" void kernel_launch(void* const* d_in, const int* in_sizes, int n_in,
                              void* d_out, int out_size) {
    const float* h0   = (const float*)d_in[1];
    const float* c0   = (const float*)d_in[2];
    const float* emb  = (const float*)d_in[3];
    const float* Wih  = (const float*)d_in[4];
    const float* Whh  = (const float*)d_in[5];
    const float* bih  = (const float*)d_in[6];
    const float* bhh  = (const float*)d_in[7];
    const float* Wout = (const float*)d_in[8];
    const float* bout = (const float*)d_in[9];
    const int*   dstw = (const int*)d_in[10];
    float* out = (float*)d_out;

    // dynamic smem for the persistent LSTM: Ws 33024 + Hs 65536 + psm 4224
    const int lstm_smem = 16 * 516 * 4 + 32 * 128 * 16 + 2 * 16 * 33 * 4;
    static int attr_done = 0;
    if (!attr_done) {
        cudaFuncSetAttribute(lstm_persistent_kernel,
                             cudaFuncAttributeMaxDynamicSharedMemorySize,
                             lstm_smem);
        attr_done = 1;
    }

    detect_kernel<<<1, 256>>>(dstw);
    prep_kernel<<<(VSZ * HSZ + 255) / 256, 256>>>(Wout, h0, c0);
    gemm1_kernel<<<dim3(GSZ / 64, MROWS / 64), 256>>>(emb, Wih, bih, bhh, dstw);
    lstm_persistent_kernel<<<NBLK, 256, lstm_smem>>>(Whh);
    gemm2_kernel<<<dim3(VSZ / 128, MROWS / 128), 256>>>(bout, out);
    logsoftmax_kernel<<<MROWS, 256>>>(out);
}

// round 9
// speedup vs baseline: 1.2571x; 1.0226x over previous
#include <cuda_runtime.h>
#include <cuda_bf16.h>
#include <math.h>
#include <stdint.h>

// Problem constants
#define T_STEPS 64
#define BATCH   32
#define HSZ     512
#define VSZ     32000
#define GSZ     2048            // 4*HSZ
#define MROWS   2048            // T*B
#define NBLK    128             // persistent LSTM grid
#define NNB     250             // gemm2 n-blocks (32000/128)

// ---------------- scratch (device globals; no allocations allowed) ----------
__device__ float          g_X[MROWS * GSZ];          // 16 MB: x-part of gates
__device__ float          g_h[2][BATCH * HSZ];       // double-buffered hidden
__device__ float          g_c[BATCH * HSZ];          // cell state (init only)
__device__ __nv_bfloat16  g_hout[MROWS * HSZ];       // all h_t in bf16 (GEMM2 A)
__device__ __nv_bfloat16  g_woutb[VSZ * HSZ];        // W_out in bf16 (GEMM2 B)
__device__ int            g_is64;                    // dst dtype flag
__device__ unsigned       g_bar;                     // grid barrier counter
__device__ float2         g_red[256 * MROWS];        // [nb][m] (max, sumexp)
__device__ float          g_logz[MROWS];             // per-m logZ

// ---------------- helpers ----------------------------------------------------
__device__ __forceinline__ void cp_async16(void* sdst, const void* gsrc) {
    uint32_t s = (uint32_t)__cvta_generic_to_shared(sdst);
    asm volatile("cp.async.cg.shared.global [%0], [%1], 16;\n"
                 :: "r"(s), "l"(gsrc) : "memory");
}
__device__ __forceinline__ void cp_async_commit_wait() {
    asm volatile("cp.async.commit_group;\n" ::: "memory");
    asm volatile("cp.async.wait_group 0;\n" ::: "memory");
}

// ---------------- dtype detect for dst (int64 vs int32) ---------------------
__global__ void detect_kernel(const int* __restrict__ dstw) {
    __shared__ int ok;
    if (threadIdx.x == 0) ok = 1;
    __syncthreads();
    for (int i = threadIdx.x; i < 1024; i += blockDim.x)
        if (dstw[2 * i + 1] != 0) ok = 0;
    __syncthreads();
    if (threadIdx.x == 0) g_is64 = ok;
}

// ---------------- prep: W_out -> bf16, copy h0/c0, reset barrier ------------
__global__ void prep_kernel(const float* __restrict__ wout,
                            const float* __restrict__ h0,
                            const float* __restrict__ c0) {
    int i = blockIdx.x * blockDim.x + threadIdx.x;
    if (i == 0) g_bar = 0u;
    if (i < VSZ * HSZ) g_woutb[i] = __float2bfloat16(wout[i]);
    if (i < BATCH * HSZ) { g_h[0][i] = h0[i]; g_c[i] = c0[i]; }
}

// ---------------- GEMM1: X = emb[dst] @ W_ih^T + (b_ih + b_hh) --------------
__global__ void __launch_bounds__(256) gemm1_kernel(
    const float* __restrict__ emb, const float* __restrict__ Wih,
    const float* __restrict__ bih, const float* __restrict__ bhh,
    const int* __restrict__ dstw) {
    __shared__ float As[64][17];
    __shared__ float Bs[64][17];
    __shared__ int   ridx[64];

    const int m0 = blockIdx.y * 64;
    const int n0 = blockIdx.x * 64;
    const int tid = threadIdx.x;

    if (tid < 64) {
        int m = m0 + tid;
        ridx[tid] = g_is64 ? dstw[2 * m] : dstw[m];
    }

    const int tx = tid & 15, ty = tid >> 4;
    const int lr = tid >> 2, kq = (tid & 3) * 4;
    float acc[4][4] = {};

    for (int kc = 0; kc < HSZ; kc += 16) {
        __syncthreads();
        {
            float4 av = *(const float4*)(emb + (size_t)ridx[lr] * HSZ + kc + kq);
            As[lr][kq + 0] = av.x; As[lr][kq + 1] = av.y;
            As[lr][kq + 2] = av.z; As[lr][kq + 3] = av.w;
            float4 bv = *(const float4*)(Wih + (size_t)(n0 + lr) * HSZ + kc + kq);
            Bs[lr][kq + 0] = bv.x; Bs[lr][kq + 1] = bv.y;
            Bs[lr][kq + 2] = bv.z; Bs[lr][kq + 3] = bv.w;
        }
        __syncthreads();
        #pragma unroll
        for (int k = 0; k < 16; k++) {
            float a[4], b[4];
            #pragma unroll
            for (int i = 0; i < 4; i++) a[i] = As[ty * 4 + i][k];
            #pragma unroll
            for (int j = 0; j < 4; j++) b[j] = Bs[tx * 4 + j][k];
            #pragma unroll
            for (int i = 0; i < 4; i++)
                #pragma unroll
                for (int j = 0; j < 4; j++)
                    acc[i][j] += a[i] * b[j];
        }
    }
    #pragma unroll
    for (int i = 0; i < 4; i++) {
        int m = m0 + ty * 4 + i;
        #pragma unroll
        for (int j = 0; j < 4; j++) {
            int n = n0 + tx * 4 + j;
            g_X[(size_t)m * GSZ + n] = acc[i][j] + bih[n] + bhh[n];
        }
    }
}

// ---------------- persistent LSTM: all 64 steps in ONE kernel ---------------
// 128 blocks x 256 threads. Block owns 4 j (16 gate rows); c in registers.
// Per step: light grid barrier (tid0 fence only), group-split cp.async h load
// (kh group loads only its K-half, synced by a named barrier), FFMA GEMV.
__global__ void __launch_bounds__(256) lstm_persistent_kernel(
    const float* __restrict__ Whh) {
    extern __shared__ float sdyn[];
    float*  Ws  = sdyn;                                  // [16][516]
    float4* Hs  = (float4*)(sdyn + 16 * 516);            // [32*128] swizzled
    float*  psm = (float*)(Hs + 32 * 128);               // [2][16][33]

    const int tid = threadIdx.x;
    const int j0  = blockIdx.x * 4;
    const int w   = tid >> 5, lane = tid & 31;
    const int kh  = w >> 2, rg = w & 3;
    const int sw  = lane & 7;
    const int tg128 = tid & 127;

    // Load this block's Whh slice into smem once (16 rows x 512).
    {
        int lr = tid >> 4;                 // 0..15
        int kq = (tid & 15) * 4;           // 0..60
        int grow = ((lr >> 2) << 9) + j0 + (lr & 3);
        #pragma unroll
        for (int kc = 0; kc < HSZ; kc += 64)
            *(float4*)&Ws[lr * 516 + kc + kq] =
                *(const float4*)(Whh + (size_t)grow * HSZ + kc + kq);
    }

    const int b_my = tid & 31, jj_my = tid >> 5;
    float c_reg = 0.f;
    if (tid < 128) c_reg = g_c[b_my * HSZ + j0 + jj_my];

    for (int t = 0; t < T_STEPS; t++) {
        // Prefetch X for this step (overlaps the barrier wait).
        float x0 = 0.f, x1 = 0.f, x2 = 0.f, x3 = 0.f;
        if (tid < 128) {
            const float* Xr = g_X + (size_t)(t * BATCH + b_my) * GSZ + j0 + jj_my;
            x0 = Xr[0]; x1 = Xr[HSZ]; x2 = Xr[2 * HSZ]; x3 = Xr[3 * HSZ];
        }

        // Grid barrier (acquire). Single-thread fence (CG grid.sync pattern).
        if (t > 0) {
            if (tid == 0) {
                unsigned target = (unsigned)NBLK * (unsigned)t;
                while (*(volatile unsigned*)&g_bar < target) { }
                __threadfence();
            }
            __syncthreads();
        }

        // Group-split h load: kh group copies only its K-half via cp.async.cg.
        {
            const float4* hsrc = (const float4*)g_h[t & 1];
            #pragma unroll
            for (int j = 0; j < 16; j++) {
                int idx = tg128 + j * 128;            // 0..2047 within half
                int b = idx >> 6, kk = idx & 63;
                int kkg = kh * 64 + kk;
                cp_async16(&Hs[b * 128 + (kkg ^ (b & 7))], hsrc + b * 128 + kkg);
            }
            cp_async_commit_wait();
            asm volatile("bar.sync %0, 128;" :: "r"(kh + 1) : "memory");
        }

        // Partial gates: 4 rows x 1 batch per lane over this warp's K-half.
        {
            float a0 = 0.f, a1 = 0.f, a2 = 0.f, a3 = 0.f;
            const float4* HsL = Hs + lane * 128;
            const float* W0 = Ws + (rg * 4 + 0) * 516 + kh * 256;
            const float* W1 = Ws + (rg * 4 + 1) * 516 + kh * 256;
            const float* W2 = Ws + (rg * 4 + 2) * 516 + kh * 256;
            const float* W3 = Ws + (rg * 4 + 3) * 516 + kh * 256;
            #pragma unroll 8
            for (int kk = 0; kk < 64; kk++) {
                float4 hv = HsL[(kh * 64 + kk) ^ sw];
                float4 v0 = *(const float4*)(W0 + kk * 4);
                float4 v1 = *(const float4*)(W1 + kk * 4);
                float4 v2 = *(const float4*)(W2 + kk * 4);
                float4 v3 = *(const float4*)(W3 + kk * 4);
                a0 += hv.x * v0.x + hv.y * v0.y + hv.z * v0.z + hv.w * v0.w;
                a1 += hv.x * v1.x + hv.y * v1.y + hv.z * v1.z + hv.w * v1.w;
                a2 += hv.x * v2.x + hv.y * v2.y + hv.z * v2.z + hv.w * v2.w;
                a3 += hv.x * v3.x + hv.y * v3.y + hv.z * v3.z + hv.w * v3.w;
            }
            psm[(kh * 16 + rg * 4 + 0) * 33 + lane] = a0;
            psm[(kh * 16 + rg * 4 + 1) * 33 + lane] = a1;
            psm[(kh * 16 + rg * 4 + 2) * 33 + lane] = a2;
            psm[(kh * 16 + rg * 4 + 3) * 33 + lane] = a3;
        }
        __syncthreads();

        // Cell update (threads 0..127 own fixed (b_my, j0+jj_my)).
        if (tid < 128) {
            float gi = x0 + psm[(0 * 4 + jj_my) * 33 + b_my]
                          + psm[(16 + 0 * 4 + jj_my) * 33 + b_my];
            float gf = x1 + psm[(1 * 4 + jj_my) * 33 + b_my]
                          + psm[(16 + 1 * 4 + jj_my) * 33 + b_my];
            float gg = x2 + psm[(2 * 4 + jj_my) * 33 + b_my]
                          + psm[(16 + 2 * 4 + jj_my) * 33 + b_my];
            float go = x3 + psm[(3 * 4 + jj_my) * 33 + b_my]
                          + psm[(16 + 3 * 4 + jj_my) * 33 + b_my];
            float si = 1.f / (1.f + __expf(-gi));
            float sf = 1.f / (1.f + __expf(-gf));
            float so = 1.f / (1.f + __expf(-go));
            float cn = sf * c_reg + si * tanhf(gg);
            float hn = so * tanhf(cn);
            c_reg = cn;
            __stcg(&g_h[(t + 1) & 1][b_my * HSZ + j0 + jj_my], hn);
            g_hout[(size_t)(t * BATCH + b_my) * HSZ + j0 + jj_my] =
                __float2bfloat16(hn);
        }
        // Grid barrier (release): single-thread fence after CTA sync.
        __syncthreads();
        if (tid == 0) { __threadfence(); atomicAdd(&g_bar, 1u); }
    }
}

// ---------------- GEMM2: logits + per-block softmax partials ----------------
__device__ __forceinline__ void mma16816(float* c, const uint32_t* a,
                                         uint32_t b0, uint32_t b1) {
    asm volatile(
        "mma.sync.aligned.m16n8k16.row.col.f32.bf16.bf16.f32 "
        "{%0,%1,%2,%3}, {%4,%5,%6,%7}, {%8,%9}, {%0,%1,%2,%3};\n"
        : "+f"(c[0]), "+f"(c[1]), "+f"(c[2]), "+f"(c[3])
        : "r"(a[0]), "r"(a[1]), "r"(a[2]), "r"(a[3]), "r"(b0), "r"(b1));
}

__global__ void __launch_bounds__(256) gemm2_kernel(
    const float* __restrict__ b_out, float* __restrict__ out) {
    __shared__ __nv_bfloat16 As[128][24];
    __shared__ __nv_bfloat16 Bs[128][24];
    __shared__ float2 sred[128][2];     // per m-row (max, sumexp) per wn

    const int tid = threadIdx.x;
    const int m0 = blockIdx.y * 128;
    const int n0 = blockIdx.x * 128;
    const int warp = tid >> 5, lane = tid & 31;
    const int wm = warp & 3, wn = warp >> 2;
    const int g = lane >> 2, tg = lane & 3;
    const int lr = tid >> 1, hf = tid & 1;

    float acc[2][8][4] = {};

    for (int kc = 0; kc < HSZ; kc += 16) {
        __syncthreads();
        *(uint4*)&As[lr][hf * 8] =
            *(const uint4*)(g_hout + (size_t)(m0 + lr) * HSZ + kc + hf * 8);
        *(uint4*)&Bs[lr][hf * 8] =
            *(const uint4*)(g_woutb + (size_t)(n0 + lr) * HSZ + kc + hf * 8);
        __syncthreads();

        uint32_t a[2][4];
        #pragma unroll
        for (int mi = 0; mi < 2; mi++) {
            int rb = wm * 32 + mi * 16;
            a[mi][0] = *(const uint32_t*)&As[rb + g][2 * tg];
            a[mi][1] = *(const uint32_t*)&As[rb + g + 8][2 * tg];
            a[mi][2] = *(const uint32_t*)&As[rb + g][2 * tg + 8];
            a[mi][3] = *(const uint32_t*)&As[rb + g + 8][2 * tg + 8];
        }
        #pragma unroll
        for (int ni = 0; ni < 8; ni++) {
            uint32_t b0 = *(const uint32_t*)&Bs[wn * 64 + ni * 8 + g][2 * tg];
            uint32_t b1 = *(const uint32_t*)&Bs[wn * 64 + ni * 8 + g][2 * tg + 8];
            mma16816(acc[0][ni], a[0], b0, b1);
            mma16816(acc[1][ni], a[1], b0, b1);
        }
    }

    // Epilogue: add bias (into acc), write transposed logits, and compute
    // per-row (max, sumexp) partials for the fused log_softmax.
    #pragma unroll
    for (int mi = 0; mi < 2; mi++) {
        int mbase = m0 + wm * 32 + mi * 16;
        #pragma unroll
        for (int ni = 0; ni < 8; ni++) {
            int n = n0 + wn * 64 + ni * 8 + 2 * tg;
            float bo0 = b_out[n], bo1 = b_out[n + 1];
            acc[mi][ni][0] += bo0; acc[mi][ni][1] += bo1;
            acc[mi][ni][2] += bo0; acc[mi][ni][3] += bo1;
            int m_a = mbase + g;
            int row_a = (m_a & 31) * T_STEPS + (m_a >> 5);
            *(float2*)(out + (size_t)row_a * VSZ + n) =
                make_float2(acc[mi][ni][0], acc[mi][ni][1]);
            int m_b = mbase + g + 8;
            int row_b = (m_b & 31) * T_STEPS + (m_b >> 5);
            *(float2*)(out + (size_t)row_b * VSZ + n) =
                make_float2(acc[mi][ni][2], acc[mi][ni][3]);
        }
        // rows (local): wm*32 + mi*16 + g (half 0) and +8 (half 1).
        #pragma unroll
        for (int half = 0; half < 2; half++) {
            float M = -3.4e38f;
            #pragma unroll
            for (int ni = 0; ni < 8; ni++) {
                M = fmaxf(M, acc[mi][ni][2 * half + 0]);
                M = fmaxf(M, acc[mi][ni][2 * half + 1]);
            }
            // the 4 lanes owning this row are a contiguous shfl group (tg)
            M = fmaxf(M, __shfl_xor_sync(0xffffffffu, M, 1));
            M = fmaxf(M, __shfl_xor_sync(0xffffffffu, M, 2));
            float S = 0.f;
            #pragma unroll
            for (int ni = 0; ni < 8; ni++) {
                S += __expf(acc[mi][ni][2 * half + 0] - M);
                S += __expf(acc[mi][ni][2 * half + 1] - M);
            }
            S += __shfl_xor_sync(0xffffffffu, S, 1);
            S += __shfl_xor_sync(0xffffffffu, S, 2);
            if (tg == 0)
                sred[wm * 32 + mi * 16 + half * 8 + g][wn] = make_float2(M, S);
        }
    }
    __syncthreads();
    if (tid < 128) {
        float2 p0 = sred[tid][0], p1 = sred[tid][1];
        float M = fmaxf(p0.x, p1.x);
        float S = p0.y * __expf(p0.x - M) + p1.y * __expf(p1.x - M);
        g_red[blockIdx.x * MROWS + m0 + tid] = make_float2(M, S);
    }
}

// ---------------- logZ reduce: 2048 rows x 250 partials ---------------------
__global__ void __launch_bounds__(256) logz_kernel() {
    int m = blockIdx.x * 256 + threadIdx.x;      // gemm M row
    float M = -3.4e38f, S = 0.f;
    for (int nb = 0; nb < NNB; nb++) {
        float2 p = g_red[nb * MROWS + m];
        float nm = fmaxf(M, p.x);
        S = S * __expf(M - nm) + p.y * __expf(p.x - nm);
        M = nm;
    }
    g_logz[m] = M + logf(S);
}

// ---------------- final: out -= logZ (single streaming pass) ----------------
__global__ void __launch_bounds__(256) sub_kernel(float* __restrict__ out) {
    int orow = blockIdx.x;                        // 0..2047 (b*64+t)
    int m = (orow & 63) * 32 + (orow >> 6);       // back to gemm M row
    float lz = g_logz[m];
    float4* r = (float4*)(out + (size_t)orow * VSZ);
    for (int i = threadIdx.x; i < VSZ / 4; i += 256) {
        float4 v = r[i];
        v.x -= lz; v.y -= lz; v.z -= lz; v.w -= lz;
        r[i] = v;
    }
}

// ---------------- launch ----------------------------------------------------
extern "C" void kernel_launch(void* const* d_in, const int* in_sizes, int n_in,
                              void* d_out, int out_size) {
    const float* h0   = (const float*)d_in[1];
    const float* c0   = (const float*)d_in[2];
    const float* emb  = (const float*)d_in[3];
    const float* Wih  = (const float*)d_in[4];
    const float* Whh  = (const float*)d_in[5];
    const float* bih  = (const float*)d_in[6];
    const float* bhh  = (const float*)d_in[7];
    const float* Wout = (const float*)d_in[8];
    const float* bout = (const float*)d_in[9];
    const int*   dstw = (const int*)d_in[10];
    float* out = (float*)d_out;

    const int lstm_smem = 16 * 516 * 4 + 32 * 128 * 16 + 2 * 16 * 33 * 4;
    static int attr_done = 0;
    if (!attr_done) {
        cudaFuncSetAttribute(lstm_persistent_kernel,
                             cudaFuncAttributeMaxDynamicSharedMemorySize,
                             lstm_smem);
        attr_done = 1;
    }

    detect_kernel<<<1, 256>>>(dstw);
    prep_kernel<<<(VSZ * HSZ + 255) / 256, 256>>>(Wout, h0, c0);
    gemm1_kernel<<<dim3(GSZ / 64, MROWS / 64), 256>>>(emb, Wih, bih, bhh, dstw);
    lstm_persistent_kernel<<<NBLK, 256, lstm_smem>>>(Whh);
    gemm2_kernel<<<dim3(VSZ / 128, MROWS / 128), 256>>>(bout, out);
    logz_kernel<<<MROWS / 256, 256>>>();
    sub_kernel<<<MROWS, 256>>>(out);
}

// round 11
// speedup vs baseline: 1.7223x; 1.3700x over previous
#include <cuda_runtime.h>
#include <cuda_bf16.h>
#include <math.h>
#include <stdint.h>

// Problem constants
#define T_STEPS 64
#define BATCH   32
#define HSZ     512
#define VSZ     32000
#define GSZ     2048            // 4*HSZ
#define MROWS   2048            // T*B
#define NBLK    128             // persistent LSTM grid
#define NNB     250             // gemm2 n-blocks (32000/128)

// ---------------- scratch (device globals; no allocations allowed) ----------
__device__ float          g_X[MROWS * GSZ];          // 16 MB: x-part of gates
__device__ float          g_c[BATCH * HSZ];          // cell state (init only)
__device__ __nv_bfloat16  g_h0b[BATCH * HSZ];        // h0 in bf16
__device__ __nv_bfloat16  g_hout[MROWS * HSZ];       // all h_t bf16 (A of gemm2)
__device__ __nv_bfloat16  g_woutb[VSZ * HSZ];        // W_out bf16
__device__ __nv_bfloat16  g_wihb[GSZ * HSZ];         // W_ih bf16
__device__ __nv_bfloat16  g_xembb[MROWS * HSZ];      // emb[dst] bf16 (gathered)
__device__ int            g_is64;                    // dst dtype flag
__device__ unsigned       g_bar;                     // grid barrier counter
__device__ float2         g_red[256 * MROWS];        // [nb][m] (max, sumexp)
__device__ float          g_logz[MROWS];             // per-m logZ

// ---------------- helpers ----------------------------------------------------
__device__ __forceinline__ void cp_async16(void* sdst, const void* gsrc) {
    uint32_t s = (uint32_t)__cvta_generic_to_shared(sdst);
    asm volatile("cp.async.cg.shared.global [%0], [%1], 16;\n"
                 :: "r"(s), "l"(gsrc) : "memory");
}
__device__ __forceinline__ void cp_async_commit_wait() {
    asm volatile("cp.async.commit_group;\n" ::: "memory");
    asm volatile("cp.async.wait_group 0;\n" ::: "memory");
}
__device__ __forceinline__ void mma16816(float* c, const uint32_t* a,
                                         uint32_t b0, uint32_t b1) {
    asm volatile(
        "mma.sync.aligned.m16n8k16.row.col.f32.bf16.bf16.f32 "
        "{%0,%1,%2,%3}, {%4,%5,%6,%7}, {%8,%9}, {%0,%1,%2,%3};\n"
        : "+f"(c[0]), "+f"(c[1]), "+f"(c[2]), "+f"(c[3])
        : "r"(a[0]), "r"(a[1]), "r"(a[2]), "r"(a[3]), "r"(b0), "r"(b1));
}

// ---------------- dtype detect for dst (int64 vs int32) ---------------------
__global__ void detect_kernel(const int* __restrict__ dstw) {
    __shared__ int ok;
    if (threadIdx.x == 0) ok = 1;
    __syncthreads();
    for (int i = threadIdx.x; i < 1024; i += blockDim.x)
        if (dstw[2 * i + 1] != 0) ok = 0;
    __syncthreads();
    if (threadIdx.x == 0) g_is64 = ok;
}

// ---------------- prep: weights -> bf16, copy h0/c0, reset barrier ----------
__global__ void prep_kernel(const float* __restrict__ wout,
                            const float* __restrict__ wih,
                            const float* __restrict__ h0,
                            const float* __restrict__ c0) {
    int i = blockIdx.x * blockDim.x + threadIdx.x;
    if (i == 0) g_bar = 0u;
    if (i < VSZ * HSZ) g_woutb[i] = __float2bfloat16(wout[i]);
    if (i < GSZ * HSZ) g_wihb[i] = __float2bfloat16(wih[i]);
    if (i < BATCH * HSZ) {
        g_h0b[i] = __float2bfloat16(h0[i]);
        g_c[i] = c0[i];
    }
}

// ---------------- gather: emb[dst] -> bf16 [2048][512] ----------------------
__global__ void __launch_bounds__(256) gather_kernel(
    const float* __restrict__ emb, const int* __restrict__ dstw) {
    int m = blockIdx.x;
    int row = g_is64 ? dstw[2 * m] : dstw[m];
    const float* src = emb + (size_t)row * HSZ;
    __nv_bfloat16* dst = g_xembb + (size_t)m * HSZ;
    for (int i = threadIdx.x; i < HSZ; i += 256)
        dst[i] = __float2bfloat16(src[i]);
}

// ---------------- GEMM1: X = xemb @ W_ih^T + (b_ih+b_hh)  (bf16 mma) --------
__global__ void __launch_bounds__(256) gemm1_kernel(
    const float* __restrict__ bih, const float* __restrict__ bhh) {
    __shared__ __nv_bfloat16 As[128][24];
    __shared__ __nv_bfloat16 Bs[128][24];

    const int tid = threadIdx.x;
    const int m0 = blockIdx.y * 128;
    const int n0 = blockIdx.x * 128;
    const int warp = tid >> 5, lane = tid & 31;
    const int wm = warp & 3, wn = warp >> 2;
    const int g = lane >> 2, tg = lane & 3;
    const int lr = tid >> 1, hf = tid & 1;

    float acc[2][8][4] = {};

    for (int kc = 0; kc < HSZ; kc += 16) {
        __syncthreads();
        *(uint4*)&As[lr][hf * 8] =
            *(const uint4*)(g_xembb + (size_t)(m0 + lr) * HSZ + kc + hf * 8);
        *(uint4*)&Bs[lr][hf * 8] =
            *(const uint4*)(g_wihb + (size_t)(n0 + lr) * HSZ + kc + hf * 8);
        __syncthreads();

        uint32_t a[2][4];
        #pragma unroll
        for (int mi = 0; mi < 2; mi++) {
            int rb = wm * 32 + mi * 16;
            a[mi][0] = *(const uint32_t*)&As[rb + g][2 * tg];
            a[mi][1] = *(const uint32_t*)&As[rb + g + 8][2 * tg];
            a[mi][2] = *(const uint32_t*)&As[rb + g][2 * tg + 8];
            a[mi][3] = *(const uint32_t*)&As[rb + g + 8][2 * tg + 8];
        }
        #pragma unroll
        for (int ni = 0; ni < 8; ni++) {
            uint32_t b0 = *(const uint32_t*)&Bs[wn * 64 + ni * 8 + g][2 * tg];
            uint32_t b1 = *(const uint32_t*)&Bs[wn * 64 + ni * 8 + g][2 * tg + 8];
            mma16816(acc[0][ni], a[0], b0, b1);
            mma16816(acc[1][ni], a[1], b0, b1);
        }
    }
    #pragma unroll
    for (int mi = 0; mi < 2; mi++) {
        int mbase = m0 + wm * 32 + mi * 16;
        #pragma unroll
        for (int ni = 0; ni < 8; ni++) {
            int n = n0 + wn * 64 + ni * 8 + 2 * tg;
            float bo0 = bih[n] + bhh[n], bo1 = bih[n + 1] + bhh[n + 1];
            *(float2*)(g_X + (size_t)(mbase + g) * GSZ + n) =
                make_float2(acc[mi][ni][0] + bo0, acc[mi][ni][1] + bo1);
            *(float2*)(g_X + (size_t)(mbase + g + 8) * GSZ + n) =
                make_float2(acc[mi][ni][2] + bo0, acc[mi][ni][3] + bo1);
        }
    }
}

// ---------------- persistent LSTM: tensor-core recurrence -------------------
__global__ void __launch_bounds__(256) lstm_persistent_kernel(
    const float* __restrict__ Whh) {
    extern __shared__ char sdyn[];
    __nv_bfloat16* As = (__nv_bfloat16*)sdyn;            // [32][520]
    __nv_bfloat16* Bs = As + 32 * 520;                   // [16][520]
    float* psum = (float*)(Bs + 16 * 520);               // [8][32][17]

    const int tid = threadIdx.x;
    const int j0  = blockIdx.x * 4;
    const int w   = tid >> 5, lane = tid & 31;
    const int g   = lane >> 2, tg = lane & 3;

    // Convert this block's Whh slice to bf16 smem once (16 rows x 512).
    for (int i = tid; i < 16 * HSZ; i += 256) {
        int lr = i >> 9, k = i & 511;                    // lr = gate*4 + jj
        int grow = ((lr >> 2) << 9) + j0 + (lr & 3);
        Bs[lr * 520 + k] = __float2bfloat16(Whh[(size_t)grow * HSZ + k]);
    }

    const int b_my = tid & 31, jj_my = tid >> 5;
    float c_reg = 0.f;
    if (tid < 128) c_reg = g_c[b_my * HSZ + j0 + jj_my];
    __syncthreads();

    for (int t = 0; t < T_STEPS; t++) {
        // Prefetch X for this step (overlaps the barrier wait).
        float x0 = 0.f, x1 = 0.f, x2 = 0.f, x3 = 0.f;
        if (tid < 128) {
            const float* Xr = g_X + (size_t)(t * BATCH + b_my) * GSZ + j0 + jj_my;
            x0 = Xr[0]; x1 = Xr[HSZ]; x2 = Xr[2 * HSZ]; x3 = Xr[3 * HSZ];
        }

        // Grid barrier (acquire); single-thread fence (CG grid.sync pattern).
        if (t > 0) {
            if (tid == 0) {
                unsigned target = (unsigned)NBLK * (unsigned)t;
                while (*(volatile unsigned*)&g_bar < target) { }
                __threadfence();
            }
            __syncthreads();
        }

        // Load h tile (32x512 bf16) into As via cp.async (8 granules/thread).
        {
            const __nv_bfloat16* hsrc =
                (t == 0) ? g_h0b : g_hout + (size_t)(t - 1) * BATCH * HSZ;
            #pragma unroll
            for (int j = 0; j < 8; j++) {
                int idx = tid + j * 256;                 // 0..2047
                int row = idx >> 6, cg = idx & 63;
                cp_async16(As + row * 520 + cg * 8, hsrc + row * HSZ + cg * 8);
            }
            cp_async_commit_wait();
            __syncthreads();
        }

        // Split-K mma: warp w covers k-tiles kt = 4w .. 4w+3.
        {
            float acc[2][2][4] = {};
            const int kb = w * 64;
            #pragma unroll
            for (int kt = 0; kt < 4; kt++) {
                int k0 = kb + kt * 16;
                uint32_t a[2][4], bb[2][2];
                #pragma unroll
                for (int mt = 0; mt < 2; mt++) {
                    a[mt][0] = *(const uint32_t*)&As[(mt * 16 + g) * 520 + k0 + 2 * tg];
                    a[mt][1] = *(const uint32_t*)&As[(mt * 16 + g + 8) * 520 + k0 + 2 * tg];
                    a[mt][2] = *(const uint32_t*)&As[(mt * 16 + g) * 520 + k0 + 2 * tg + 8];
                    a[mt][3] = *(const uint32_t*)&As[(mt * 16 + g + 8) * 520 + k0 + 2 * tg + 8];
                }
                #pragma unroll
                for (int ni = 0; ni < 2; ni++) {
                    bb[ni][0] = *(const uint32_t*)&Bs[(ni * 8 + g) * 520 + k0 + 2 * tg];
                    bb[ni][1] = *(const uint32_t*)&Bs[(ni * 8 + g) * 520 + k0 + 2 * tg + 8];
                }
                #pragma unroll
                for (int mt = 0; mt < 2; mt++)
                    #pragma unroll
                    for (int ni = 0; ni < 2; ni++)
                        mma16816(acc[mt][ni], a[mt], bb[ni][0], bb[ni][1]);
            }
            // Split-K partials: psum[w][batch 0..31][col 0..15], row pad 17.
            float* pw = psum + w * (32 * 17);
            #pragma unroll
            for (int mt = 0; mt < 2; mt++)
                #pragma unroll
                for (int ni = 0; ni < 2; ni++) {
                    int m = mt * 16 + g, n = ni * 8 + 2 * tg;
                    pw[m * 17 + n]           = acc[mt][ni][0];
                    pw[m * 17 + n + 1]       = acc[mt][ni][1];
                    pw[(m + 8) * 17 + n]     = acc[mt][ni][2];
                    pw[(m + 8) * 17 + n + 1] = acc[mt][ni][3];
                }
        }
        __syncthreads();

        // Cell update (threads 0..127 own fixed (b_my, j0+jj_my)).
        if (tid < 128) {
            float s0 = x0, s1 = x1, s2 = x2, s3 = x3;
            #pragma unroll
            for (int ww = 0; ww < 8; ww++) {
                const float* p = psum + ww * (32 * 17) + b_my * 17;
                s0 += p[jj_my];      s1 += p[4 + jj_my];
                s2 += p[8 + jj_my];  s3 += p[12 + jj_my];
            }
            float si = 1.f / (1.f + __expf(-s0));
            float sf = 1.f / (1.f + __expf(-s1));
            float so = 1.f / (1.f + __expf(-s3));
            float cn = sf * c_reg + si * tanhf(s2);
            float hn = so * tanhf(cn);
            c_reg = cn;
            __nv_bfloat16 hb = __float2bfloat16(hn);
            __stcg((unsigned short*)&g_hout[(size_t)(t * BATCH + b_my) * HSZ
                                            + j0 + jj_my],
                   *(unsigned short*)&hb);
        }
        // Grid barrier (release): single-thread fence after CTA sync.
        __syncthreads();
        if (tid == 0) { __threadfence(); atomicAdd(&g_bar, 1u); }
    }
}

// ---------------- GEMM2: logits + per-block softmax partials ----------------
__global__ void __launch_bounds__(256) gemm2_kernel(
    const float* __restrict__ b_out, float* __restrict__ out) {
    __shared__ __nv_bfloat16 As[128][24];
    __shared__ __nv_bfloat16 Bs[128][24];
    __shared__ float2 sred[128][2];

    const int tid = threadIdx.x;
    const int m0 = blockIdx.y * 128;
    const int n0 = blockIdx.x * 128;
    const int warp = tid >> 5, lane = tid & 31;
    const int wm = warp & 3, wn = warp >> 2;
    const int g = lane >> 2, tg = lane & 3;
    const int lr = tid >> 1, hf = tid & 1;

    float acc[2][8][4] = {};

    for (int kc = 0; kc < HSZ; kc += 16) {
        __syncthreads();
        *(uint4*)&As[lr][hf * 8] =
            *(const uint4*)(g_hout + (size_t)(m0 + lr) * HSZ + kc + hf * 8);
        *(uint4*)&Bs[lr][hf * 8] =
            *(const uint4*)(g_woutb + (size_t)(n0 + lr) * HSZ + kc + hf * 8);
        __syncthreads();

        uint32_t a[2][4];
        #pragma unroll
        for (int mi = 0; mi < 2; mi++) {
            int rb = wm * 32 + mi * 16;
            a[mi][0] = *(const uint32_t*)&As[rb + g][2 * tg];
            a[mi][1] = *(const uint32_t*)&As[rb + g + 8][2 * tg];
            a[mi][2] = *(const uint32_t*)&As[rb + g][2 * tg + 8];
            a[mi][3] = *(const uint32_t*)&As[rb + g + 8][2 * tg + 8];
        }
        #pragma unroll
        for (int ni = 0; ni < 8; ni++) {
            uint32_t b0 = *(const uint32_t*)&Bs[wn * 64 + ni * 8 + g][2 * tg];
            uint32_t b1 = *(const uint32_t*)&Bs[wn * 64 + ni * 8 + g][2 * tg + 8];
            mma16816(acc[0][ni], a[0], b0, b1);
            mma16816(acc[1][ni], a[1], b0, b1);
        }
    }

    #pragma unroll
    for (int mi = 0; mi < 2; mi++) {
        int mbase = m0 + wm * 32 + mi * 16;
        #pragma unroll
        for (int ni = 0; ni < 8; ni++) {
            int n = n0 + wn * 64 + ni * 8 + 2 * tg;
            float bo0 = b_out[n], bo1 = b_out[n + 1];
            acc[mi][ni][0] += bo0; acc[mi][ni][1] += bo1;
            acc[mi][ni][2] += bo0; acc[mi][ni][3] += bo1;
            int m_a = mbase + g;
            int row_a = (m_a & 31) * T_STEPS + (m_a >> 5);
            *(float2*)(out + (size_t)row_a * VSZ + n) =
                make_float2(acc[mi][ni][0], acc[mi][ni][1]);
            int m_b = mbase + g + 8;
            int row_b = (m_b & 31) * T_STEPS + (m_b >> 5);
            *(float2*)(out + (size_t)row_b * VSZ + n) =
                make_float2(acc[mi][ni][2], acc[mi][ni][3]);
        }
        #pragma unroll
        for (int half = 0; half < 2; half++) {
            float M = -3.4e38f;
            #pragma unroll
            for (int ni = 0; ni < 8; ni++) {
                M = fmaxf(M, acc[mi][ni][2 * half + 0]);
                M = fmaxf(M, acc[mi][ni][2 * half + 1]);
            }
            M = fmaxf(M, __shfl_xor_sync(0xffffffffu, M, 1));
            M = fmaxf(M, __shfl_xor_sync(0xffffffffu, M, 2));
            float S = 0.f;
            #pragma unroll
            for (int ni = 0; ni < 8; ni++) {
                S += __expf(acc[mi][ni][2 * half + 0] - M);
                S += __expf(acc[mi][ni][2 * half + 1] - M);
            }
            S += __shfl_xor_sync(0xffffffffu, S, 1);
            S += __shfl_xor_sync(0xffffffffu, S, 2);
            if (tg == 0)
                sred[wm * 32 + mi * 16 + half * 8 + g][wn] = make_float2(M, S);
        }
    }
    __syncthreads();
    if (tid < 128) {
        float2 p0 = sred[tid][0], p1 = sred[tid][1];
        float M = fmaxf(p0.x, p1.x);
        float S = p0.y * __expf(p0.x - M) + p1.y * __expf(p1.x - M);
        g_red[blockIdx.x * MROWS + m0 + tid] = make_float2(M, S);
    }
}

// ---------------- logZ reduce: 2048 rows x 250 partials ---------------------
__global__ void __launch_bounds__(256) logz_kernel() {
    int m = blockIdx.x * 256 + threadIdx.x;
    float M = -3.4e38f, S = 0.f;
    for (int nb = 0; nb < NNB; nb++) {
        float2 p = g_red[nb * MROWS + m];
        float nm = fmaxf(M, p.x);
        S = S * __expf(M - nm) + p.y * __expf(p.x - nm);
        M = nm;
    }
    g_logz[m] = M + logf(S);
}

// ---------------- final: out -= logZ (single streaming pass) ----------------
__global__ void __launch_bounds__(256) sub_kernel(float* __restrict__ out) {
    int orow = blockIdx.x;
    int m = (orow & 63) * 32 + (orow >> 6);
    float lz = g_logz[m];
    float4* r = (float4*)(out + (size_t)orow * VSZ);
    for (int i = threadIdx.x; i < VSZ / 4; i += 256) {
        float4 v = r[i];
        v.x -= lz; v.y -= lz; v.z -= lz; v.w -= lz;
        r[i] = v;
    }
}

// ---------------- launch ----------------------------------------------------
extern "C" void kernel_launch(void* const* d_in, const int* in_sizes, int n_in,
                              void* d_out, int out_size) {
    const float* h0   = (const float*)d_in[1];
    const float* c0   = (const float*)d_in[2];
    const float* emb  = (const float*)d_in[3];
    const float* Wih  = (const float*)d_in[4];
    const float* Whh  = (const float*)d_in[5];
    const float* bih  = (const float*)d_in[6];
    const float* bhh  = (const float*)d_in[7];
    const float* Wout = (const float*)d_in[8];
    const float* bout = (const float*)d_in[9];
    const int*   dstw = (const int*)d_in[10];
    float* out = (float*)d_out;

    const int lstm_smem = 32 * 520 * 2 + 16 * 520 * 2 + 8 * 32 * 17 * 4;
    static int attr_done = 0;
    if (!attr_done) {
        cudaFuncSetAttribute(lstm_persistent_kernel,
                             cudaFuncAttributeMaxDynamicSharedMemorySize,
                             lstm_smem);
        attr_done = 1;
    }

    detect_kernel<<<1, 256>>>(dstw);
    prep_kernel<<<(VSZ * HSZ + 255) / 256, 256>>>(Wout, Wih, h0, c0);
    gather_kernel<<<MROWS, 256>>>(emb, dstw);
    gemm1_kernel<<<dim3(GSZ / 128, MROWS / 128), 256>>>(bih, bhh);
    lstm_persistent_kernel<<<NBLK, 256, lstm_smem>>>(Whh);
    gemm2_kernel<<<dim3(VSZ / 128, MROWS / 128), 256>>>(bout, out);
    logz_kernel<<<MROWS / 256, 256>>>();
    sub_kernel<<<MROWS, 256>>>(out);
}

// round 14
// speedup vs baseline: 2.0237x; 1.1750x over previous
#include <cuda_runtime.h>
#include <cuda_bf16.h>
#include <math.h>
#include <stdint.h>

// Problem constants
#define T_STEPS 64
#define BATCH   32
#define HSZ     512
#define VSZ     32000
#define GSZ     2048            // 4*HSZ
#define MROWS   2048            // T*B
#define NBLK    128             // persistent LSTM grid
#define NNB     250             // gemm2 n-blocks (32000/128)

// ---------------- scratch (device globals; no allocations allowed) ----------
__device__ float          g_X[MROWS * GSZ];          // 16 MB: x-part of gates
__device__ float          g_c[BATCH * HSZ];          // cell state (init only)
__device__ __nv_bfloat16  g_h0b[BATCH * HSZ];        // h0 in bf16
__device__ __nv_bfloat16  g_hout[MROWS * HSZ];       // all h_t bf16 (A of gemm2)
__device__ __nv_bfloat16  g_woutb[VSZ * HSZ];        // W_out bf16
__device__ __nv_bfloat16  g_wihb[GSZ * HSZ];         // W_ih bf16
__device__ __nv_bfloat16  g_xembb[MROWS * HSZ];      // emb[dst] bf16 (gathered)
__device__ int            g_is64;                    // dst dtype flag
__device__ unsigned       g_bar;                     // grid barrier counter
__device__ float2         g_red[256 * MROWS];        // [nb][m] (max, sumexp)
__device__ float          g_logz[MROWS];             // per-m logZ

// ---------------- helpers ----------------------------------------------------
__device__ __forceinline__ void cp_async16(void* sdst, const void* gsrc) {
    uint32_t s = (uint32_t)__cvta_generic_to_shared(sdst);
    asm volatile("cp.async.cg.shared.global [%0], [%1], 16;\n"
                 :: "r"(s), "l"(gsrc) : "memory");
}
__device__ __forceinline__ void cp_async_commit() {
    asm volatile("cp.async.commit_group;\n" ::: "memory");
}
__device__ __forceinline__ void cp_async_commit_wait() {
    asm volatile("cp.async.commit_group;\n" ::: "memory");
    asm volatile("cp.async.wait_group 0;\n" ::: "memory");
}
__device__ __forceinline__ void mma16816(float* c, const uint32_t* a,
                                         uint32_t b0, uint32_t b1) {
    asm volatile(
        "mma.sync.aligned.m16n8k16.row.col.f32.bf16.bf16.f32 "
        "{%0,%1,%2,%3}, {%4,%5,%6,%7}, {%8,%9}, {%0,%1,%2,%3};\n"
        : "+f"(c[0]), "+f"(c[1]), "+f"(c[2]), "+f"(c[3])
        : "r"(a[0]), "r"(a[1]), "r"(a[2]), "r"(a[3]), "r"(b0), "r"(b1));
}
__device__ __forceinline__ void ldsm_x4(uint32_t& r0, uint32_t& r1,
                                        uint32_t& r2, uint32_t& r3,
                                        const void* p) {
    uint32_t a = (uint32_t)__cvta_generic_to_shared(p);
    asm volatile("ldmatrix.sync.aligned.m8n8.x4.shared.b16 {%0,%1,%2,%3}, [%4];"
                 : "=r"(r0), "=r"(r1), "=r"(r2), "=r"(r3) : "r"(a));
}

// ---------------- dtype detect for dst (int64 vs int32) ---------------------
__global__ void detect_kernel(const int* __restrict__ dstw) {
    __shared__ int ok;
    if (threadIdx.x == 0) ok = 1;
    __syncthreads();
    for (int i = threadIdx.x; i < 1024; i += blockDim.x)
        if (dstw[2 * i + 1] != 0) ok = 0;
    __syncthreads();
    if (threadIdx.x == 0) g_is64 = ok;
}

// ---------------- prep: weights -> bf16, copy h0/c0, reset barrier ----------
__global__ void prep_kernel(const float* __restrict__ wout,
                            const float* __restrict__ wih,
                            const float* __restrict__ h0,
                            const float* __restrict__ c0) {
    int i = blockIdx.x * blockDim.x + threadIdx.x;
    if (i == 0) g_bar = 0u;
    if (i < VSZ * HSZ) g_woutb[i] = __float2bfloat16(wout[i]);
    if (i < GSZ * HSZ) g_wihb[i] = __float2bfloat16(wih[i]);
    if (i < BATCH * HSZ) {
        g_h0b[i] = __float2bfloat16(h0[i]);
        g_c[i] = c0[i];
    }
}

// ---------------- gather: emb[dst] -> bf16 [2048][512] ----------------------
__global__ void __launch_bounds__(256) gather_kernel(
    const float* __restrict__ emb, const int* __restrict__ dstw) {
    int m = blockIdx.x;
    int row = g_is64 ? dstw[2 * m] : dstw[m];
    const float* src = emb + (size_t)row * HSZ;
    __nv_bfloat16* dst = g_xembb + (size_t)m * HSZ;
    for (int i = threadIdx.x; i < HSZ; i += 256)
        dst[i] = __float2bfloat16(src[i]);
}

// =============================================================================
// Shared GEMM core pieces: 128x128 block, BK=32, 2-stage cp.async pipeline,
// ldmatrix.x4 fragment loads from pad-40 smem (conflict-free LDSM phases).
// Warp layout: 8 warps = 4(m) x 2(n); warp tile 32(m) x 64(n).
// =============================================================================

// loads one BK=32 slab of A and B into stage st (2 granules each per thread)
#define GEMM_LOAD_STAGE(As, Bs, st, Aptr, Bptr, kc)                          \
    do {                                                                     \
        int row_ = tid >> 1;                                                 \
        int gc_ = (tid & 1) * 16;                                            \
        cp_async16(&As[st][row_][gc_],                                       \
                   Aptr + (size_t)(m0 + row_) * HSZ + (kc) + gc_);           \
        cp_async16(&As[st][row_][gc_ + 8],                                   \
                   Aptr + (size_t)(m0 + row_) * HSZ + (kc) + gc_ + 8);       \
        cp_async16(&Bs[st][row_][gc_],                                       \
                   Bptr + (size_t)(n0 + row_) * HSZ + (kc) + gc_);           \
        cp_async16(&Bs[st][row_][gc_ + 8],                                   \
                   Bptr + (size_t)(n0 + row_) * HSZ + (kc) + gc_ + 8);       \
    } while (0)

// compute on stage st: 2 k-chunks of 16, ldmatrix frags, 32 HMMA per warp
#define GEMM_COMPUTE_STAGE(As, Bs, st)                                       \
    do {                                                                     \
        _Pragma("unroll")                                                    \
        for (int kk = 0; kk < 32; kk += 16) {                                \
            uint32_t a_[2][4];                                               \
            _Pragma("unroll")                                                \
            for (int mi = 0; mi < 2; mi++)                                   \
                ldsm_x4(a_[mi][0], a_[mi][1], a_[mi][2], a_[mi][3],          \
                        &As[st][wm * 32 + mi * 16 + (lane & 15)]             \
                            [kk + (lane >> 4) * 8]);                         \
            uint32_t b_[8][2];                                               \
            _Pragma("unroll")                                                \
            for (int p = 0; p < 4; p++) {                                    \
                uint32_t r0, r1, r2, r3;                                     \
                ldsm_x4(r0, r1, r2, r3,                                      \
                        &Bs[st][wn * 64 + p * 16 + (lane & 7) +              \
                                (lane >> 4) * 8]                             \
                            [kk + ((lane >> 3) & 1) * 8]);                   \
                b_[2 * p][0] = r0; b_[2 * p][1] = r1;                        \
                b_[2 * p + 1][0] = r2; b_[2 * p + 1][1] = r3;                \
            }                                                                \
            _Pragma("unroll")                                                \
            for (int ni = 0; ni < 8; ni++) {                                 \
                mma16816(acc[0][ni], a_[0], b_[ni][0], b_[ni][1]);           \
                mma16816(acc[1][ni], a_[1], b_[ni][0], b_[ni][1]);           \
            }                                                                \
        }                                                                    \
    } while (0)

// ---------------- GEMM1: X = xemb @ W_ih^T + (b_ih+b_hh) --------------------
__global__ void __launch_bounds__(256, 2) gemm1_kernel(
    const float* __restrict__ bih, const float* __restrict__ bhh) {
    __shared__ __nv_bfloat16 As[2][128][40];
    __shared__ __nv_bfloat16 Bs[2][128][40];

    const int tid = threadIdx.x;
    const int m0 = blockIdx.y * 128;
    const int n0 = blockIdx.x * 128;
    const int warp = tid >> 5, lane = tid & 31;
    const int wm = warp & 3, wn = warp >> 2;
    const int g = lane >> 2, tg = lane & 3;

    float acc[2][8][4] = {};

    GEMM_LOAD_STAGE(As, Bs, 0, g_xembb, g_wihb, 0);
    cp_async_commit();
    for (int kc = 0; kc < HSZ; kc += 32) {
        int st = (kc >> 5) & 1;
        if (kc + 32 < HSZ) {
            GEMM_LOAD_STAGE(As, Bs, st ^ 1, g_xembb, g_wihb, kc + 32);
            cp_async_commit();
            asm volatile("cp.async.wait_group 1;\n" ::: "memory");
        } else {
            asm volatile("cp.async.wait_group 0;\n" ::: "memory");
        }
        __syncthreads();
        GEMM_COMPUTE_STAGE(As, Bs, st);
        __syncthreads();
    }

    #pragma unroll
    for (int mi = 0; mi < 2; mi++) {
        int mbase = m0 + wm * 32 + mi * 16;
        #pragma unroll
        for (int ni = 0; ni < 8; ni++) {
            int n = n0 + wn * 64 + ni * 8 + 2 * tg;
            float bo0 = bih[n] + bhh[n], bo1 = bih[n + 1] + bhh[n + 1];
            *(float2*)(g_X + (size_t)(mbase + g) * GSZ + n) =
                make_float2(acc[mi][ni][0] + bo0, acc[mi][ni][1] + bo1);
            *(float2*)(g_X + (size_t)(mbase + g + 8) * GSZ + n) =
                make_float2(acc[mi][ni][2] + bo0, acc[mi][ni][3] + bo1);
        }
    }
}

// ---------------- persistent LSTM: tensor-core recurrence -------------------
__global__ void __launch_bounds__(256) lstm_persistent_kernel(
    const float* __restrict__ Whh) {
    extern __shared__ char sdyn[];
    __nv_bfloat16* Ah = (__nv_bfloat16*)sdyn;            // [32][520]
    __nv_bfloat16* Bh = Ah + 32 * 520;                   // [16][520]
    float* psum = (float*)(Bh + 16 * 520);               // [8][32][17]

    const int tid = threadIdx.x;
    const int j0  = blockIdx.x * 4;
    const int w   = tid >> 5, lane = tid & 31;
    const int g   = lane >> 2, tg = lane & 3;

    // Convert this block's Whh slice to bf16 smem once (16 rows x 512).
    for (int i = tid; i < 16 * HSZ; i += 256) {
        int lr = i >> 9, k = i & 511;                    // lr = gate*4 + jj
        int grow = ((lr >> 2) << 9) + j0 + (lr & 3);
        Bh[lr * 520 + k] = __float2bfloat16(Whh[(size_t)grow * HSZ + k]);
    }

    const int b_my = tid & 31, jj_my = tid >> 5;
    float c_reg = 0.f;
    if (tid < 128) c_reg = g_c[b_my * HSZ + j0 + jj_my];
    __syncthreads();

    for (int t = 0; t < T_STEPS; t++) {
        // Prefetch X for this step (overlaps the barrier wait).
        float x0 = 0.f, x1 = 0.f, x2 = 0.f, x3 = 0.f;
        if (tid < 128) {
            const float* Xr = g_X + (size_t)(t * BATCH + b_my) * GSZ + j0 + jj_my;
            x0 = Xr[0]; x1 = Xr[HSZ]; x2 = Xr[2 * HSZ]; x3 = Xr[3 * HSZ];
        }

        // Grid barrier (acquire); single-thread fence (CG grid.sync pattern).
        if (t > 0) {
            if (tid == 0) {
                unsigned target = (unsigned)NBLK * (unsigned)t;
                while (*(volatile unsigned*)&g_bar < target) { }
                __threadfence();
            }
            __syncthreads();
        }

        // Load h tile (32x512 bf16) into Ah via cp.async (8 granules/thread).
        {
            const __nv_bfloat16* hsrc =
                (t == 0) ? g_h0b : g_hout + (size_t)(t - 1) * BATCH * HSZ;
            #pragma unroll
            for (int j = 0; j < 8; j++) {
                int idx = tid + j * 256;                 // 0..2047
                int row = idx >> 6, cg = idx & 63;
                cp_async16(Ah + row * 520 + cg * 8, hsrc + row * HSZ + cg * 8);
            }
            cp_async_commit_wait();
            __syncthreads();
        }

        // Split-K mma: warp w covers k-tiles kt = 4w .. 4w+3.
        {
            float acc[2][2][4] = {};
            const int kb = w * 64;
            #pragma unroll
            for (int kt = 0; kt < 4; kt++) {
                int k0 = kb + kt * 16;
                uint32_t a[2][4], bb[2][2];
                #pragma unroll
                for (int mt = 0; mt < 2; mt++) {
                    a[mt][0] = *(const uint32_t*)&Ah[(mt * 16 + g) * 520 + k0 + 2 * tg];
                    a[mt][1] = *(const uint32_t*)&Ah[(mt * 16 + g + 8) * 520 + k0 + 2 * tg];
                    a[mt][2] = *(const uint32_t*)&Ah[(mt * 16 + g) * 520 + k0 + 2 * tg + 8];
                    a[mt][3] = *(const uint32_t*)&Ah[(mt * 16 + g + 8) * 520 + k0 + 2 * tg + 8];
                }
                #pragma unroll
                for (int ni = 0; ni < 2; ni++) {
                    bb[ni][0] = *(const uint32_t*)&Bh[(ni * 8 + g) * 520 + k0 + 2 * tg];
                    bb[ni][1] = *(const uint32_t*)&Bh[(ni * 8 + g) * 520 + k0 + 2 * tg + 8];
                }
                #pragma unroll
                for (int mt = 0; mt < 2; mt++)
                    #pragma unroll
                    for (int ni = 0; ni < 2; ni++)
                        mma16816(acc[mt][ni], a[mt], bb[ni][0], bb[ni][1]);
            }
            // Split-K partials: psum[w][batch 0..31][col 0..15], row pad 17.
            float* pw = psum + w * (32 * 17);
            #pragma unroll
            for (int mt = 0; mt < 2; mt++)
                #pragma unroll
                for (int ni = 0; ni < 2; ni++) {
                    int m = mt * 16 + g, n = ni * 8 + 2 * tg;
                    pw[m * 17 + n]           = acc[mt][ni][0];
                    pw[m * 17 + n + 1]       = acc[mt][ni][1];
                    pw[(m + 8) * 17 + n]     = acc[mt][ni][2];
                    pw[(m + 8) * 17 + n + 1] = acc[mt][ni][3];
                }
        }
        __syncthreads();

        // Cell update (threads 0..127 own fixed (b_my, j0+jj_my)).
        if (tid < 128) {
            float s0 = x0, s1 = x1, s2 = x2, s3 = x3;
            #pragma unroll
            for (int ww = 0; ww < 8; ww++) {
                const float* p = psum + ww * (32 * 17) + b_my * 17;
                s0 += p[jj_my];      s1 += p[4 + jj_my];
                s2 += p[8 + jj_my];  s3 += p[12 + jj_my];
            }
            float si = 1.f / (1.f + __expf(-s0));
            float sf = 1.f / (1.f + __expf(-s1));
            float so = 1.f / (1.f + __expf(-s3));
            float cn = sf * c_reg + si * tanhf(s2);
            float hn = so * tanhf(cn);
            c_reg = cn;
            __nv_bfloat16 hb = __float2bfloat16(hn);
            __stcg((unsigned short*)&g_hout[(size_t)(t * BATCH + b_my) * HSZ
                                            + j0 + jj_my],
                   *(unsigned short*)&hb);
        }
        // Grid barrier (release): single-thread fence after CTA sync.
        __syncthreads();
        if (tid == 0) { __threadfence(); atomicAdd(&g_bar, 1u); }
    }
}

// ---------------- GEMM2: logits + per-block softmax partials ----------------
__global__ void __launch_bounds__(256, 2) gemm2_kernel(
    const float* __restrict__ b_out, float* __restrict__ out) {
    __shared__ __nv_bfloat16 As[2][128][40];
    __shared__ __nv_bfloat16 Bs[2][128][40];
    __shared__ float2 sred[128][2];

    const int tid = threadIdx.x;
    const int m0 = blockIdx.y * 128;
    const int n0 = blockIdx.x * 128;
    const int warp = tid >> 5, lane = tid & 31;
    const int wm = warp & 3, wn = warp >> 2;
    const int g = lane >> 2, tg = lane & 3;

    float acc[2][8][4] = {};

    GEMM_LOAD_STAGE(As, Bs, 0, g_hout, g_woutb, 0);
    cp_async_commit();
    for (int kc = 0; kc < HSZ; kc += 32) {
        int st = (kc >> 5) & 1;
        if (kc + 32 < HSZ) {
            GEMM_LOAD_STAGE(As, Bs, st ^ 1, g_hout, g_woutb, kc + 32);
            cp_async_commit();
            asm volatile("cp.async.wait_group 1;\n" ::: "memory");
        } else {
            asm volatile("cp.async.wait_group 0;\n" ::: "memory");
        }
        __syncthreads();
        GEMM_COMPUTE_STAGE(As, Bs, st);
        __syncthreads();
    }

    // Epilogue: add bias, write transposed logits, fused softmax partials.
    #pragma unroll
    for (int mi = 0; mi < 2; mi++) {
        int mbase = m0 + wm * 32 + mi * 16;
        #pragma unroll
        for (int ni = 0; ni < 8; ni++) {
            int n = n0 + wn * 64 + ni * 8 + 2 * tg;
            float bo0 = b_out[n], bo1 = b_out[n + 1];
            acc[mi][ni][0] += bo0; acc[mi][ni][1] += bo1;
            acc[mi][ni][2] += bo0; acc[mi][ni][3] += bo1;
            int m_a = mbase + g;
            int row_a = (m_a & 31) * T_STEPS + (m_a >> 5);
            *(float2*)(out + (size_t)row_a * VSZ + n) =
                make_float2(acc[mi][ni][0], acc[mi][ni][1]);
            int m_b = mbase + g + 8;
            int row_b = (m_b & 31) * T_STEPS + (m_b >> 5);
            *(float2*)(out + (size_t)row_b * VSZ + n) =
                make_float2(acc[mi][ni][2], acc[mi][ni][3]);
        }
        #pragma unroll
        for (int half = 0; half < 2; half++) {
            float M = -3.4e38f;
            #pragma unroll
            for (int ni = 0; ni < 8; ni++) {
                M = fmaxf(M, acc[mi][ni][2 * half + 0]);
                M = fmaxf(M, acc[mi][ni][2 * half + 1]);
            }
            M = fmaxf(M, __shfl_xor_sync(0xffffffffu, M, 1));
            M = fmaxf(M, __shfl_xor_sync(0xffffffffu, M, 2));
            float S = 0.f;
            #pragma unroll
            for (int ni = 0; ni < 8; ni++) {
                S += __expf(acc[mi][ni][2 * half + 0] - M);
                S += __expf(acc[mi][ni][2 * half + 1] - M);
            }
            S += __shfl_xor_sync(0xffffffffu, S, 1);
            S += __shfl_xor_sync(0xffffffffu, S, 2);
            if (tg == 0)
                sred[wm * 32 + mi * 16 + half * 8 + g][wn] = make_float2(M, S);
        }
    }
    __syncthreads();
    if (tid < 128) {
        float2 p0 = sred[tid][0], p1 = sred[tid][1];
        float M = fmaxf(p0.x, p1.x);
        float S = p0.y * __expf(p0.x - M) + p1.y * __expf(p1.x - M);
        g_red[blockIdx.x * MROWS + m0 + tid] = make_float2(M, S);
    }
}

// ---------------- logZ reduce: 2048 rows x 250 partials ---------------------
__global__ void __launch_bounds__(256) logz_kernel() {
    int m = blockIdx.x * 256 + threadIdx.x;
    float M = -3.4e38f, S = 0.f;
    for (int nb = 0; nb < NNB; nb++) {
        float2 p = g_red[nb * MROWS + m];
        float nm = fmaxf(M, p.x);
        S = S * __expf(M - nm) + p.y * __expf(p.x - nm);
        M = nm;
    }
    g_logz[m] = M + logf(S);
}

// ---------------- final: out -= logZ (single streaming pass) ----------------
__global__ void __launch_bounds__(256) sub_kernel(float* __restrict__ out) {
    int orow = blockIdx.x;
    int m = (orow & 63) * 32 + (orow >> 6);
    float lz = g_logz[m];
    float4* r = (float4*)(out + (size_t)orow * VSZ);
    for (int i = threadIdx.x; i < VSZ / 4; i += 256) {
        float4 v = r[i];
        v.x -= lz; v.y -= lz; v.z -= lz; v.w -= lz;
        r[i] = v;
    }
}

// ---------------- launch ----------------------------------------------------
extern "C" void kernel_launch(void* const* d_in, const int* in_sizes, int n_in,
                              void* d_out, int out_size) {
    const float* h0   = (const float*)d_in[1];
    const float* c0   = (const float*)d_in[2];
    const float* emb  = (const float*)d_in[3];
    const float* Wih  = (const float*)d_in[4];
    const float* Whh  = (const float*)d_in[5];
    const float* bih  = (const float*)d_in[6];
    const float* bhh  = (const float*)d_in[7];
    const float* Wout = (const float*)d_in[8];
    const float* bout = (const float*)d_in[9];
    const int*   dstw = (const int*)d_in[10];
    float* out = (float*)d_out;

    const int lstm_smem = 32 * 520 * 2 + 16 * 520 * 2 + 8 * 32 * 17 * 4;
    static int attr_done = 0;
    if (!attr_done) {
        cudaFuncSetAttribute(lstm_persistent_kernel,
                             cudaFuncAttributeMaxDynamicSharedMemorySize,
                             lstm_smem);
        attr_done = 1;
    }

    detect_kernel<<<1, 256>>>(dstw);
    prep_kernel<<<(VSZ * HSZ + 255) / 256, 256>>>(Wout, Wih, h0, c0);
    gather_kernel<<<MROWS, 256>>>(emb, dstw);
    gemm1_kernel<<<dim3(GSZ / 128, MROWS / 128), 256>>>(bih, bhh);
    lstm_persistent_kernel<<<NBLK, 256, lstm_smem>>>(Whh);
    gemm2_kernel<<<dim3(VSZ / 128, MROWS / 128), 256>>>(bout, out);
    logz_kernel<<<MROWS / 256, 256>>>();
    sub_kernel<<<MROWS, 256>>>(out);
}

// round 16
// speedup vs baseline: 2.2860x; 1.1296x over previous
#include <cuda_runtime.h>
#include <cuda_bf16.h>
#include <cuda_fp16.h>
#include <math.h>
#include <stdint.h>

// Problem constants
#define T_STEPS 64
#define BATCH   32
#define HSZ     512
#define VSZ     32000
#define GSZ     2048            // 4*HSZ
#define MROWS   2048            // T*B
#define NBLK    128             // persistent LSTM grid
#define NNB     250             // gemm2 n-blocks (32000/128)
#define NSLAB   16              // K slabs of 32 (HSZ/32)

// ---------------- scratch (device globals; no allocations allowed) ----------
__device__ float          g_X[MROWS * GSZ];          // 16 MB: x-part of gates
__device__ float          g_c[BATCH * HSZ];          // cell state (init only)
__device__ __nv_bfloat16  g_h0b[BATCH * HSZ];        // h0 in bf16
__device__ __nv_bfloat16  g_hout[MROWS * HSZ];       // all h_t bf16 (A of gemm2)
__device__ __nv_bfloat16  g_woutb[VSZ * HSZ];        // W_out bf16
__device__ __nv_bfloat16  g_wihb[GSZ * HSZ];         // W_ih bf16
__device__ __nv_bfloat16  g_xembb[MROWS * HSZ];      // emb[dst] bf16 (gathered)
__device__ __half         g_logith[(size_t)MROWS * VSZ];  // 128 MB fp16 logits
__device__ int            g_is64;                    // dst dtype flag
__device__ unsigned       g_bar;                     // grid barrier counter
__device__ float2         g_red[256 * MROWS];        // [nb][m] (max, sumexp)
__device__ float          g_logz[MROWS];             // per-m logZ

// ---------------- helpers ----------------------------------------------------
__device__ __forceinline__ void cp_async16(void* sdst, const void* gsrc) {
    uint32_t s = (uint32_t)__cvta_generic_to_shared(sdst);
    asm volatile("cp.async.cg.shared.global [%0], [%1], 16;\n"
                 :: "r"(s), "l"(gsrc) : "memory");
}
__device__ __forceinline__ void cp_async_commit() {
    asm volatile("cp.async.commit_group;\n" ::: "memory");
}
__device__ __forceinline__ void cp_async_commit_wait() {
    asm volatile("cp.async.commit_group;\n" ::: "memory");
    asm volatile("cp.async.wait_group 0;\n" ::: "memory");
}
__device__ __forceinline__ void mma16816(float* c, const uint32_t* a,
                                         uint32_t b0, uint32_t b1) {
    asm volatile(
        "mma.sync.aligned.m16n8k16.row.col.f32.bf16.bf16.f32 "
        "{%0,%1,%2,%3}, {%4,%5,%6,%7}, {%8,%9}, {%0,%1,%2,%3};\n"
        : "+f"(c[0]), "+f"(c[1]), "+f"(c[2]), "+f"(c[3])
        : "r"(a[0]), "r"(a[1]), "r"(a[2]), "r"(a[3]), "r"(b0), "r"(b1));
}
__device__ __forceinline__ void ldsm_x4(uint32_t& r0, uint32_t& r1,
                                        uint32_t& r2, uint32_t& r3,
                                        const void* p) {
    uint32_t a = (uint32_t)__cvta_generic_to_shared(p);
    asm volatile("ldmatrix.sync.aligned.m8n8.x4.shared.b16 {%0,%1,%2,%3}, [%4];"
                 : "=r"(r0), "=r"(r1), "=r"(r2), "=r"(r3) : "r"(a));
}

// ---------------- dtype detect for dst (int64 vs int32) ---------------------
__global__ void detect_kernel(const int* __restrict__ dstw) {
    __shared__ int ok;
    if (threadIdx.x == 0) ok = 1;
    __syncthreads();
    for (int i = threadIdx.x; i < 1024; i += blockDim.x)
        if (dstw[2 * i + 1] != 0) ok = 0;
    __syncthreads();
    if (threadIdx.x == 0) g_is64 = ok;
}

// ---------------- prep: weights -> bf16, copy h0/c0, reset barrier ----------
__global__ void prep_kernel(const float* __restrict__ wout,
                            const float* __restrict__ wih,
                            const float* __restrict__ h0,
                            const float* __restrict__ c0) {
    int i = blockIdx.x * blockDim.x + threadIdx.x;
    if (i == 0) g_bar = 0u;
    if (i < VSZ * HSZ) g_woutb[i] = __float2bfloat16(wout[i]);
    if (i < GSZ * HSZ) g_wihb[i] = __float2bfloat16(wih[i]);
    if (i < BATCH * HSZ) {
        g_h0b[i] = __float2bfloat16(h0[i]);
        g_c[i] = c0[i];
    }
}

// ---------------- gather: emb[dst] -> bf16 [2048][512] ----------------------
__global__ void __launch_bounds__(256) gather_kernel(
    const float* __restrict__ emb, const int* __restrict__ dstw) {
    int m = blockIdx.x;
    int row = g_is64 ? dstw[2 * m] : dstw[m];
    const float* src = emb + (size_t)row * HSZ;
    __nv_bfloat16* dst = g_xembb + (size_t)m * HSZ;
    for (int i = threadIdx.x; i < HSZ; i += 256)
        dst[i] = __float2bfloat16(src[i]);
}

// =============================================================================
// GEMM core: 128x128 block, BK=32, FOUR-stage cp.async pipeline, ldmatrix.x4
// frags from pad-40 smem. 8 warps = 4(m) x 2(n); warp tile 32(m) x 64(n).
// One __syncthreads per slab (multistage invariant: after sync at iter i, all
// warps finished stage i-1, whose buffer is the overwrite target (i+3)&3).
// =============================================================================

typedef __nv_bfloat16 (*SmemTile)[128][40];

#define GEMM_LOAD_STAGE(As, Bs, st, Aptr, Bptr, kc)                          \
    do {                                                                     \
        int row_ = tid >> 1;                                                 \
        int gc_ = (tid & 1) * 16;                                            \
        cp_async16(&As[st][row_][gc_],                                       \
                   Aptr + (size_t)(m0 + row_) * HSZ + (kc) + gc_);           \
        cp_async16(&As[st][row_][gc_ + 8],                                   \
                   Aptr + (size_t)(m0 + row_) * HSZ + (kc) + gc_ + 8);       \
        cp_async16(&Bs[st][row_][gc_],                                       \
                   Bptr + (size_t)(n0 + row_) * HSZ + (kc) + gc_);           \
        cp_async16(&Bs[st][row_][gc_ + 8],                                   \
                   Bptr + (size_t)(n0 + row_) * HSZ + (kc) + gc_ + 8);       \
    } while (0)

#define GEMM_COMPUTE_STAGE(As, Bs, st)                                       \
    do {                                                                     \
        _Pragma("unroll")                                                    \
        for (int kk = 0; kk < 32; kk += 16) {                                \
            uint32_t a_[2][4];                                               \
            _Pragma("unroll")                                                \
            for (int mi = 0; mi < 2; mi++)                                   \
                ldsm_x4(a_[mi][0], a_[mi][1], a_[mi][2], a_[mi][3],          \
                        &As[st][wm * 32 + mi * 16 + (lane & 15)]             \
                            [kk + (lane >> 4) * 8]);                         \
            uint32_t b_[8][2];                                               \
            _Pragma("unroll")                                                \
            for (int p = 0; p < 4; p++) {                                    \
                uint32_t r0, r1, r2, r3;                                     \
                ldsm_x4(r0, r1, r2, r3,                                      \
                        &Bs[st][wn * 64 + p * 16 + (lane & 7) +              \
                                (lane >> 4) * 8]                             \
                            [kk + ((lane >> 3) & 1) * 8]);                   \
                b_[2 * p][0] = r0; b_[2 * p][1] = r1;                        \
                b_[2 * p + 1][0] = r2; b_[2 * p + 1][1] = r3;                \
            }                                                                \
            _Pragma("unroll")                                                \
            for (int ni = 0; ni < 8; ni++) {                                 \
                mma16816(acc[0][ni], a_[0], b_[ni][0], b_[ni][1]);           \
                mma16816(acc[1][ni], a_[1], b_[ni][0], b_[ni][1]);           \
            }                                                                \
        }                                                                    \
    } while (0)

#define GEMM_MAINLOOP(As, Bs, Aptr, Bptr)                                    \
    do {                                                                     \
        GEMM_LOAD_STAGE(As, Bs, 0, Aptr, Bptr, 0);  cp_async_commit();       \
        GEMM_LOAD_STAGE(As, Bs, 1, Aptr, Bptr, 32); cp_async_commit();       \
        GEMM_LOAD_STAGE(As, Bs, 2, Aptr, Bptr, 64); cp_async_commit();       \
        for (int it = 0; it < NSLAB; it++) {                                 \
            asm volatile("cp.async.wait_group 2;\n" ::: "memory");           \
            __syncthreads();                                                 \
            if (it + 3 < NSLAB)                                              \
                GEMM_LOAD_STAGE(As, Bs, (it + 3) & 3, Aptr, Bptr,            \
                                (it + 3) * 32);                              \
            cp_async_commit();                                               \
            GEMM_COMPUTE_STAGE(As, Bs, it & 3);                              \
        }                                                                    \
    } while (0)

#define GEMM_SMEM_BYTES (4 * 2 * 128 * 40 * 2)   // 81920

// ---------------- GEMM1: X = xemb @ W_ih^T + (b_ih+b_hh) --------------------
__global__ void __launch_bounds__(256, 2) gemm1_kernel(
    const float* __restrict__ bih, const float* __restrict__ bhh) {
    extern __shared__ __nv_bfloat16 smem_g[];
    SmemTile As = (SmemTile)smem_g;
    SmemTile Bs = (SmemTile)(smem_g + 4 * 128 * 40);

    const int tid = threadIdx.x;
    const int m0 = blockIdx.y * 128;
    const int n0 = blockIdx.x * 128;
    const int warp = tid >> 5, lane = tid & 31;
    const int wm = warp & 3, wn = warp >> 2;
    const int g = lane >> 2, tg = lane & 3;

    float acc[2][8][4] = {};

    GEMM_MAINLOOP(As, Bs, g_xembb, g_wihb);

    #pragma unroll
    for (int mi = 0; mi < 2; mi++) {
        int mbase = m0 + wm * 32 + mi * 16;
        #pragma unroll
        for (int ni = 0; ni < 8; ni++) {
            int n = n0 + wn * 64 + ni * 8 + 2 * tg;
            float bo0 = bih[n] + bhh[n], bo1 = bih[n + 1] + bhh[n + 1];
            *(float2*)(g_X + (size_t)(mbase + g) * GSZ + n) =
                make_float2(acc[mi][ni][0] + bo0, acc[mi][ni][1] + bo1);
            *(float2*)(g_X + (size_t)(mbase + g + 8) * GSZ + n) =
                make_float2(acc[mi][ni][2] + bo0, acc[mi][ni][3] + bo1);
        }
    }
}

// ---------------- persistent LSTM: tensor-core recurrence -------------------
__global__ void __launch_bounds__(256) lstm_persistent_kernel(
    const float* __restrict__ Whh) {
    extern __shared__ char sdyn[];
    __nv_bfloat16* Ah = (__nv_bfloat16*)sdyn;            // [32][520]
    __nv_bfloat16* Bh = Ah + 32 * 520;                   // [16][520]
    float* psum = (float*)(Bh + 16 * 520);               // [8][32][17]

    const int tid = threadIdx.x;
    const int j0  = blockIdx.x * 4;
    const int w   = tid >> 5, lane = tid & 31;
    const int g   = lane >> 2, tg = lane & 3;

    // Convert this block's Whh slice to bf16 smem once (16 rows x 512).
    for (int i = tid; i < 16 * HSZ; i += 256) {
        int lr = i >> 9, k = i & 511;                    // lr = gate*4 + jj
        int grow = ((lr >> 2) << 9) + j0 + (lr & 3);
        Bh[lr * 520 + k] = __float2bfloat16(Whh[(size_t)grow * HSZ + k]);
    }

    const int b_my = tid & 31, jj_my = tid >> 5;
    float c_reg = 0.f;
    if (tid < 128) c_reg = g_c[b_my * HSZ + j0 + jj_my];
    __syncthreads();

    for (int t = 0; t < T_STEPS; t++) {
        // Prefetch X for this step (overlaps the barrier wait).
        float x0 = 0.f, x1 = 0.f, x2 = 0.f, x3 = 0.f;
        if (tid < 128) {
            const float* Xr = g_X + (size_t)(t * BATCH + b_my) * GSZ + j0 + jj_my;
            x0 = Xr[0]; x1 = Xr[HSZ]; x2 = Xr[2 * HSZ]; x3 = Xr[3 * HSZ];
        }

        // Grid barrier (acquire): tid0 polls with ld.acquire.gpu.
        if (t > 0) {
            if (tid == 0) {
                unsigned target = (unsigned)NBLK * (unsigned)t;
                unsigned v;
                do {
                    asm volatile("ld.acquire.gpu.global.u32 %0, [%1];"
                                 : "=r"(v) : "l"(&g_bar) : "memory");
                } while (v < target);
            }
            __syncthreads();
        }

        // Load h tile (32x512 bf16) into Ah via cp.async (8 granules/thread).
        {
            const __nv_bfloat16* hsrc =
                (t == 0) ? g_h0b : g_hout + (size_t)(t - 1) * BATCH * HSZ;
            #pragma unroll
            for (int j = 0; j < 8; j++) {
                int idx = tid + j * 256;                 // 0..2047
                int row = idx >> 6, cg = idx & 63;
                cp_async16(Ah + row * 520 + cg * 8, hsrc + row * HSZ + cg * 8);
            }
            cp_async_commit_wait();
            __syncthreads();
        }

        // Split-K mma: warp w covers k-tiles kt = 4w .. 4w+3.
        {
            float acc[2][2][4] = {};
            const int kb = w * 64;
            #pragma unroll
            for (int kt = 0; kt < 4; kt++) {
                int k0 = kb + kt * 16;
                uint32_t a[2][4], bb[2][2];
                #pragma unroll
                for (int mt = 0; mt < 2; mt++) {
                    a[mt][0] = *(const uint32_t*)&Ah[(mt * 16 + g) * 520 + k0 + 2 * tg];
                    a[mt][1] = *(const uint32_t*)&Ah[(mt * 16 + g + 8) * 520 + k0 + 2 * tg];
                    a[mt][2] = *(const uint32_t*)&Ah[(mt * 16 + g) * 520 + k0 + 2 * tg + 8];
                    a[mt][3] = *(const uint32_t*)&Ah[(mt * 16 + g + 8) * 520 + k0 + 2 * tg + 8];
                }
                #pragma unroll
                for (int ni = 0; ni < 2; ni++) {
                    bb[ni][0] = *(const uint32_t*)&Bh[(ni * 8 + g) * 520 + k0 + 2 * tg];
                    bb[ni][1] = *(const uint32_t*)&Bh[(ni * 8 + g) * 520 + k0 + 2 * tg + 8];
                }
                #pragma unroll
                for (int mt = 0; mt < 2; mt++)
                    #pragma unroll
                    for (int ni = 0; ni < 2; ni++)
                        mma16816(acc[mt][ni], a[mt], bb[ni][0], bb[ni][1]);
            }
            // Split-K partials: psum[w][batch 0..31][col 0..15], row pad 17.
            float* pw = psum + w * (32 * 17);
            #pragma unroll
            for (int mt = 0; mt < 2; mt++)
                #pragma unroll
                for (int ni = 0; ni < 2; ni++) {
                    int m = mt * 16 + g, n = ni * 8 + 2 * tg;
                    pw[m * 17 + n]           = acc[mt][ni][0];
                    pw[m * 17 + n + 1]       = acc[mt][ni][1];
                    pw[(m + 8) * 17 + n]     = acc[mt][ni][2];
                    pw[(m + 8) * 17 + n + 1] = acc[mt][ni][3];
                }
        }
        __syncthreads();

        // Cell update (threads 0..127 own fixed (b_my, j0+jj_my)).
        if (tid < 128) {
            float s0 = x0, s1 = x1, s2 = x2, s3 = x3;
            #pragma unroll
            for (int ww = 0; ww < 8; ww++) {
                const float* p = psum + ww * (32 * 17) + b_my * 17;
                s0 += p[jj_my];      s1 += p[4 + jj_my];
                s2 += p[8 + jj_my];  s3 += p[12 + jj_my];
            }
            float si = 1.f / (1.f + __expf(-s0));
            float sf = 1.f / (1.f + __expf(-s1));
            float so = 1.f / (1.f + __expf(-s3));
            float cn = sf * c_reg + si * tanhf(s2);
            float hn = so * tanhf(cn);
            c_reg = cn;
            __nv_bfloat16 hb = __float2bfloat16(hn);
            __stcg((unsigned short*)&g_hout[(size_t)(t * BATCH + b_my) * HSZ
                                            + j0 + jj_my],
                   *(unsigned short*)&hb);
        }
        // Grid barrier (release): syncthreads then one red.release.gpu.
        __syncthreads();
        if (tid == 0)
            asm volatile("red.release.gpu.global.add.u32 [%0], %1;"
                         :: "l"(&g_bar), "r"(1u) : "memory");
    }
}

// ---------------- GEMM2: fp16 logits + per-block softmax partials -----------
__global__ void __launch_bounds__(256, 2) gemm2_kernel(
    const float* __restrict__ b_out) {
    extern __shared__ __nv_bfloat16 smem_g[];
    SmemTile As = (SmemTile)smem_g;
    SmemTile Bs = (SmemTile)(smem_g + 4 * 128 * 40);
    __shared__ float2 sred[128][2];

    const int tid = threadIdx.x;
    const int m0 = blockIdx.y * 128;
    const int n0 = blockIdx.x * 128;
    const int warp = tid >> 5, lane = tid & 31;
    const int wm = warp & 3, wn = warp >> 2;
    const int g = lane >> 2, tg = lane & 3;

    float acc[2][8][4] = {};

    GEMM_MAINLOOP(As, Bs, g_hout, g_woutb);

    // Epilogue: add bias, write transposed fp16 logits, softmax partials.
    #pragma unroll
    for (int mi = 0; mi < 2; mi++) {
        int mbase = m0 + wm * 32 + mi * 16;
        #pragma unroll
        for (int ni = 0; ni < 8; ni++) {
            int n = n0 + wn * 64 + ni * 8 + 2 * tg;
            float bo0 = b_out[n], bo1 = b_out[n + 1];
            acc[mi][ni][0] += bo0; acc[mi][ni][1] += bo1;
            acc[mi][ni][2] += bo0; acc[mi][ni][3] += bo1;
            int m_a = mbase + g;
            int row_a = (m_a & 31) * T_STEPS + (m_a >> 5);
            *(__half2*)(g_logith + (size_t)row_a * VSZ + n) =
                __floats2half2_rn(acc[mi][ni][0], acc[mi][ni][1]);
            int m_b = mbase + g + 8;
            int row_b = (m_b & 31) * T_STEPS + (m_b >> 5);
            *(__half2*)(g_logith + (size_t)row_b * VSZ + n) =
                __floats2half2_rn(acc[mi][ni][2], acc[mi][ni][3]);
        }
        #pragma unroll
        for (int half = 0; half < 2; half++) {
            float M = -3.4e38f;
            #pragma unroll
            for (int ni = 0; ni < 8; ni++) {
                M = fmaxf(M, acc[mi][ni][2 * half + 0]);
                M = fmaxf(M, acc[mi][ni][2 * half + 1]);
            }
            M = fmaxf(M, __shfl_xor_sync(0xffffffffu, M, 1));
            M = fmaxf(M, __shfl_xor_sync(0xffffffffu, M, 2));
            float S = 0.f;
            #pragma unroll
            for (int ni = 0; ni < 8; ni++) {
                S += __expf(acc[mi][ni][2 * half + 0] - M);
                S += __expf(acc[mi][ni][2 * half + 1] - M);
            }
            S += __shfl_xor_sync(0xffffffffu, S, 1);
            S += __shfl_xor_sync(0xffffffffu, S, 2);
            if (tg == 0)
                sred[wm * 32 + mi * 16 + half * 8 + g][wn] = make_float2(M, S);
        }
    }
    __syncthreads();
    if (tid < 128) {
        float2 p0 = sred[tid][0], p1 = sred[tid][1];
        float M = fmaxf(p0.x, p1.x);
        float S = p0.y * __expf(p0.x - M) + p1.y * __expf(p1.x - M);
        g_red[blockIdx.x * MROWS + m0 + tid] = make_float2(M, S);
    }
}

// ---------------- logZ reduce: 2048 rows x 250 partials ---------------------
__global__ void __launch_bounds__(256) logz_kernel() {
    int m = blockIdx.x * 256 + threadIdx.x;
    float M = -3.4e38f, S = 0.f;
    for (int nb = 0; nb < NNB; nb++) {
        float2 p = g_red[nb * MROWS + m];
        float nm = fmaxf(M, p.x);
        S = S * __expf(M - nm) + p.y * __expf(p.x - nm);
        M = nm;
    }
    g_logz[m] = M + logf(S);
}

// ---------------- final: out = half(logit) - logZ (fp16 read, fp32 write) ---
__global__ void __launch_bounds__(256) sub_kernel(float* __restrict__ out) {
    int orow = blockIdx.x;                        // 0..2047 (b*64+t)
    int m = (orow & 63) * 32 + (orow >> 6);       // back to gemm M row
    float lz = g_logz[m];
    const __half2* src = (const __half2*)(g_logith + (size_t)orow * VSZ);
    float4* dst = (float4*)(out + (size_t)orow * VSZ);
    for (int i = threadIdx.x; i < VSZ / 4; i += 256) {
        float2 f01 = __half22float2(src[2 * i]);
        float2 f23 = __half22float2(src[2 * i + 1]);
        float4 v;
        v.x = f01.x - lz; v.y = f01.y - lz;
        v.z = f23.x - lz; v.w = f23.y - lz;
        dst[i] = v;
    }
}

// ---------------- launch ----------------------------------------------------
extern "C" void kernel_launch(void* const* d_in, const int* in_sizes, int n_in,
                              void* d_out, int out_size) {
    const float* h0   = (const float*)d_in[1];
    const float* c0   = (const float*)d_in[2];
    const float* emb  = (const float*)d_in[3];
    const float* Wih  = (const float*)d_in[4];
    const float* Whh  = (const float*)d_in[5];
    const float* bih  = (const float*)d_in[6];
    const float* bhh  = (const float*)d_in[7];
    const float* Wout = (const float*)d_in[8];
    const float* bout = (const float*)d_in[9];
    const int*   dstw = (const int*)d_in[10];
    float* out = (float*)d_out;

    const int lstm_smem = 32 * 520 * 2 + 16 * 520 * 2 + 8 * 32 * 17 * 4;
    static int attr_done = 0;
    if (!attr_done) {
        cudaFuncSetAttribute(lstm_persistent_kernel,
                             cudaFuncAttributeMaxDynamicSharedMemorySize,
                             lstm_smem);
        cudaFuncSetAttribute(gemm1_kernel,
                             cudaFuncAttributeMaxDynamicSharedMemorySize,
                             GEMM_SMEM_BYTES);
        cudaFuncSetAttribute(gemm2_kernel,
                             cudaFuncAttributeMaxDynamicSharedMemorySize,
                             GEMM_SMEM_BYTES);
        attr_done = 1;
    }

    detect_kernel<<<1, 256>>>(dstw);
    prep_kernel<<<(VSZ * HSZ + 255) / 256, 256>>>(Wout, Wih, h0, c0);
    gather_kernel<<<MROWS, 256>>>(emb, dstw);
    gemm1_kernel<<<dim3(GSZ / 128, MROWS / 128), 256, GEMM_SMEM_BYTES>>>(
        bih, bhh);
    lstm_persistent_kernel<<<NBLK, 256, lstm_smem>>>(Whh);
    gemm2_kernel<<<dim3(VSZ / 128, MROWS / 128), 256, GEMM_SMEM_BYTES>>>(bout);
    logz_kernel<<<MROWS / 256, 256>>>();
    sub_kernel<<<MROWS, 256>>>(out);
}